// round 5
// baseline (speedup 1.0000x reference)
#include <cuda_runtime.h>
#include <string.h>

#define NN 100000
#define EE 1600000
#define DD 128
#define HH 8

typedef unsigned long long ull;

// ---------------- scratch (device globals; no allocations allowed) ----------
__device__ __align__(16) float g_h[NN * DD];     // current hidden state
__device__ __align__(16) float g_xh[NN * DD];    // per-layer transformed features
__device__ float g_es[NN * HH];                  // per-node src attention logits
__device__ float g_ed[NN * HH];                  // per-node dst attention logits
__device__ int   g_deg[NN];
__device__ int   g_off[NN + 1];
__device__ int   g_cur[NN];
__device__ int   g_csr[EE];                      // src ids grouped by dst
__device__ int   g_bsum[128];                    // scan block totals
__device__ int   g_boff[128];                    // scan block offsets
__device__ double g_part[1024 * DD];             // pooling partials
__device__ __align__(16) float g_Wt_in[256 * DD];    // W_in transposed [K=256][128]
__device__ __align__(16) float g_Wt_gat[4 * DD * DD];// gat_W transposed per layer

// ---------------- weight transpose + degree zeroing (one launch) ------------
__global__ void transpose_weights(const float* __restrict__ Win,
                                  const float* __restrict__ gw) {
    int idx = blockIdx.x * blockDim.x + threadIdx.x;
    if (idx < 256 * 128) {
        int n = idx & 127;
        int k = idx >> 7;                 // 0..255
        g_Wt_in[k * 128 + n] = Win[n * 256 + k];
    } else if (idx < 98304) {
        int r = idx - 256 * 128;          // 0..65535
        int n = r & 127;
        int t = r >> 7;
        int k = t & 127;
        int l = t >> 7;
        g_Wt_gat[l * 16384 + k * 128 + n] = gw[l * 16384 + n * 128 + k];
    } else if (idx - 98304 < NN) {
        g_deg[idx - 98304] = 0;
    }
}

__device__ __forceinline__ float2 unpack2(ull v) {
    float2 f;
    memcpy(&f, &v, 8);
    return f;
}

// ---------------- GEMM: C[M,128] = A[M,K] @ Wt[K,128] (+bias) ---------------
// BM=128, BN=128, BK=32. 256 threads, 8x8 per-thread tile, packed fp32x2 FMA.
// B smem is XOR-swizzled in 16B units for conflict-free LDS.128; A smem uses
// stride 129 (conflict-free transposed scalar stores, broadcast scalar reads).
// Optionally fuses the per-head attention-logit dot products into the epilogue.
template <int K, bool ATTN>
__global__ void __launch_bounds__(256, 2)
gemm_kernel(const float* __restrict__ A, const float* __restrict__ Wt,
            const float* __restrict__ bias, float* __restrict__ C, int M,
            const float* __restrict__ asrc, const float* __restrict__ adst) {
    constexpr int BM = 128, BN = 128, BK = 32;
    constexpr int AS = 129;  // odd stride -> (k+m)%32 banks, conflict-free STS
    extern __shared__ float smem[];
    float* As = smem;            // [BK][AS]
    float* Bs = smem + BK * AS;  // [BK][BN], 16B-unit swizzled

    int tid = threadIdx.x;
    int tx = tid & 15;   // col group: cols tx*8 .. tx*8+7
    int ty = tid >> 4;   // row group: rows ty*8 .. ty*8+7
    int row0 = blockIdx.x * BM;

    // swizzle: 16B unit u stored at u ^ ((u>>3)&1). Our two units are 2tx,2tx+1
    // (same 32B pair) -> either identity or swapped within the pair.
    int bswz = (tx >> 2) & 1;
    int boff0 = tx * 8 + bswz * 4;        // float offset of logical cols 8tx..+3
    int boff1 = tx * 8 + 4 - bswz * 4;    // float offset of logical cols 8tx+4..+7

    ull acc[8][4];  // 8 rows x 4 col-pairs
#pragma unroll
    for (int i = 0; i < 8; ++i)
#pragma unroll
        for (int j = 0; j < 4; ++j) acc[i][j] = 0ull;

    for (int kk = 0; kk < K; kk += BK) {
        // A tile: 128x32, scalar coalesced loads, transposed conflict-free store
#pragma unroll
        for (int i = 0; i < (BM * BK) / 256; ++i) {
            int lin = tid + i * 256;
            int k = lin & (BK - 1);
            int m = lin >> 5;
            int row = row0 + m;
            float v = (row < M) ? A[(long)row * K + kk + k] : 0.f;
            As[k * AS + m] = v;
        }
        // B tile: 32x128 floats as float4, stored at swizzled 16B unit
#pragma unroll
        for (int i = 0; i < (BK * BN) / (256 * 4); ++i) {
            int lin = tid + i * 256;
            int n4 = lin & 31;
            int k = lin >> 5;
            int phys = n4 ^ ((n4 >> 3) & 1);
            float4 v = *(const float4*)&Wt[(kk + k) * BN + n4 * 4];
            *(float4*)&Bs[k * BN + phys * 4] = v;
        }
        __syncthreads();
#pragma unroll 4
        for (int k = 0; k < BK; ++k) {
            const float* brow = &Bs[k * BN];
            ulonglong2 u0 = *(const ulonglong2*)(brow + boff0); // cols 0-3
            ulonglong2 u1 = *(const ulonglong2*)(brow + boff1); // cols 4-7
            const float* arow = &As[k * AS + ty * 8];
#pragma unroll
            for (int i = 0; i < 8; ++i) {
                float a = arow[i];
                ull ap;
                asm("mov.b64 %0, {%1, %1};" : "=l"(ap) : "f"(a));
                asm("fma.rn.f32x2 %0, %1, %2, %0;"
                    : "+l"(acc[i][0]) : "l"(ap), "l"(u0.x));
                asm("fma.rn.f32x2 %0, %1, %2, %0;"
                    : "+l"(acc[i][1]) : "l"(ap), "l"(u0.y));
                asm("fma.rn.f32x2 %0, %1, %2, %0;"
                    : "+l"(acc[i][2]) : "l"(ap), "l"(u1.x));
                asm("fma.rn.f32x2 %0, %1, %2, %0;"
                    : "+l"(acc[i][3]) : "l"(ap), "l"(u1.y));
            }
        }
        __syncthreads();
    }

    float4 bv0 = make_float4(0.f, 0.f, 0.f, 0.f);
    float4 bv1 = bv0;
    if (bias) {
        bv0 = ((const float4*)bias)[tx * 2];
        bv1 = ((const float4*)bias)[tx * 2 + 1];
    }

    float4 as0, as1, ad0, ad1;
    if (ATTN) {
        as0 = ((const float4*)asrc)[tx * 2];
        as1 = ((const float4*)asrc)[tx * 2 + 1];
        ad0 = ((const float4*)adst)[tx * 2];
        ad1 = ((const float4*)adst)[tx * 2 + 1];
    }

#pragma unroll
    for (int i = 0; i < 8; ++i) {
        int row = row0 + ty * 8 + i;
        float2 p0 = unpack2(acc[i][0]);
        float2 p1 = unpack2(acc[i][1]);
        float2 p2 = unpack2(acc[i][2]);
        float2 p3 = unpack2(acc[i][3]);
        float4 o0, o1;
        o0.x = p0.x + bv0.x; o0.y = p0.y + bv0.y;
        o0.z = p1.x + bv0.z; o0.w = p1.y + bv0.w;
        o1.x = p2.x + bv1.x; o1.y = p2.y + bv1.y;
        o1.z = p3.x + bv1.z; o1.w = p3.y + bv1.w;
        if (row < M) {
            *(float4*)&C[(long)row * 128 + tx * 8] = o0;
            *(float4*)&C[(long)row * 128 + tx * 8 + 4] = o1;
        }
        if (ATTN) {
            // head = tx>>1; thread pair (tx, tx^1) covers the head's 16 channels
            float s = o0.x * as0.x + o0.y * as0.y + o0.z * as0.z + o0.w * as0.w
                    + o1.x * as1.x + o1.y * as1.y + o1.z * as1.z + o1.w * as1.w;
            float t = o0.x * ad0.x + o0.y * ad0.y + o0.z * ad0.z + o0.w * ad0.w
                    + o1.x * ad1.x + o1.y * ad1.y + o1.z * ad1.z + o1.w * ad1.w;
            s += __shfl_xor_sync(0xffffffffu, s, 1);
            t += __shfl_xor_sync(0xffffffffu, t, 1);
            if (row < M && (tx & 1) == 0) {
                int h = tx >> 1;
                g_es[row * 8 + h] = s;
                g_ed[row * 8 + h] = t;
            }
        }
    }
}

// ---------------- CSR build --------------------------------------------------
__global__ void hist_kernel(const int* __restrict__ dst) {
    for (int i = blockIdx.x * blockDim.x + threadIdx.x; i < EE;
         i += gridDim.x * blockDim.x)
        atomicAdd(&g_deg[dst[i]], 1);
}

// multi-block exclusive scan: pass1 local scan, pass2 block sums, pass3 offsets
__global__ void scan_pass1() {  // grid 98, block 1024
    __shared__ int wsum[32];
    int tid = threadIdx.x, lane = tid & 31, wid = tid >> 5;
    int idx = blockIdx.x * 1024 + tid;
    int v = (idx < NN) ? g_deg[idx] : 0;
    int x = v;
#pragma unroll
    for (int o = 1; o < 32; o <<= 1) {
        int t = __shfl_up_sync(0xffffffffu, x, o);
        if (lane >= o) x += t;
    }
    if (lane == 31) wsum[wid] = x;
    __syncthreads();
    if (wid == 0) {
        int y = wsum[lane];
#pragma unroll
        for (int o = 1; o < 32; o <<= 1) {
            int t = __shfl_up_sync(0xffffffffu, y, o);
            if (lane >= o) y += t;
        }
        wsum[lane] = y;
    }
    __syncthreads();
    int pre = (wid > 0) ? wsum[wid - 1] : 0;
    int incl = pre + x;
    if (idx < NN) g_off[idx] = incl - v;   // block-local exclusive
    if (tid == 1023) g_bsum[blockIdx.x] = incl;
}

__global__ void scan_pass2() {  // 1 block, 128 threads (>= 98 block sums)
    __shared__ int wsum[4];
    int tid = threadIdx.x, lane = tid & 31, wid = tid >> 5;
    int v = (tid < 98) ? g_bsum[tid] : 0;
    int x = v;
#pragma unroll
    for (int o = 1; o < 32; o <<= 1) {
        int t = __shfl_up_sync(0xffffffffu, x, o);
        if (lane >= o) x += t;
    }
    if (lane == 31) wsum[wid] = x;
    __syncthreads();
    if (tid == 0) {
        int a = 0;
#pragma unroll
        for (int i = 0; i < 4; ++i) { int t = wsum[i]; wsum[i] = a; a += t; }
    }
    __syncthreads();
    int incl = wsum[wid] + x;
    if (tid < 98) g_boff[tid] = incl - v;
    if (tid == 127) g_off[NN] = incl;
}

__global__ void scan_pass3() {  // grid 98, block 1024
    int idx = blockIdx.x * 1024 + threadIdx.x;
    if (idx < NN) {
        int o = g_off[idx] + g_boff[blockIdx.x];
        g_off[idx] = o;
        g_cur[idx] = o;
    }
}

__global__ void scatter_kernel(const int* __restrict__ src,
                               const int* __restrict__ dst) {
    for (int i = blockIdx.x * blockDim.x + threadIdx.x; i < EE;
         i += gridDim.x * blockDim.x) {
        int d = dst[i];
        int p = atomicAdd(&g_cur[d], 1);
        g_csr[p] = src[i];
    }
}

// ---------------- fused aggregate + residual + LayerNorm --------------------
// one warp per dst node; lane owns channels [4*lane, 4*lane+4); head = lane/4.
// Softmax without max-shift (logits are provably tiny here; shift-invariant).
__global__ void __launch_bounds__(256)
aggregate_kernel(const float* __restrict__ gbias, const float* __restrict__ lng,
                 const float* __restrict__ lnb, float* __restrict__ hout) {
    int lane = threadIdx.x & 31;
    int n = blockIdx.x * 8 + (threadIdx.x >> 5);
    int head = lane >> 2;
    const float4* xh4 = (const float4*)g_xh;

    float edn = g_ed[n * 8 + head];
    float e0 = g_es[n * 8 + head] + edn;
    e0 = (e0 > 0.f) ? e0 : 0.2f * e0;
    float w0 = __expf(e0);

    float d = w0;
    float4 sv = xh4[n * 32 + lane];
    float4 acc;
    acc.x = w0 * sv.x; acc.y = w0 * sv.y; acc.z = w0 * sv.z; acc.w = w0 * sv.w;

    int beg = g_off[n], end = g_off[n + 1];
#pragma unroll 4
    for (int j = beg; j < end; ++j) {
        int s = g_csr[j];
        float e = __ldg(&g_es[s * 8 + head]) + edn;
        e = (e > 0.f) ? e : 0.2f * e;
        float w = __expf(e);
        float4 v = xh4[s * 32 + lane];
        acc.x = fmaf(w, v.x, acc.x);
        acc.y = fmaf(w, v.y, acc.y);
        acc.z = fmaf(w, v.z, acc.z);
        acc.w = fmaf(w, v.w, acc.w);
        d += w;
    }
    float invd = 1.f / (d + 1e-16f);

    const float4* hin4 = (const float4*)g_h;
    float4 h0 = hin4[n * 32 + lane];
    float4 b4 = ((const float4*)gbias)[lane];
    float4 v;
    v.x = h0.x + acc.x * invd + b4.x;
    v.y = h0.y + acc.y * invd + b4.y;
    v.z = h0.z + acc.z * invd + b4.z;
    v.w = h0.w + acc.w * invd + b4.w;

    // LayerNorm across the warp's 128 values
    float s1 = v.x + v.y + v.z + v.w;
#pragma unroll
    for (int o = 16; o; o >>= 1) s1 += __shfl_xor_sync(0xffffffffu, s1, o);
    float mean = s1 * (1.f / 128.f);
    float cx = v.x - mean, cy = v.y - mean, cz = v.z - mean, cw = v.w - mean;
    float s2 = cx * cx + cy * cy + cz * cz + cw * cw;
#pragma unroll
    for (int o = 16; o; o >>= 1) s2 += __shfl_xor_sync(0xffffffffu, s2, o);
    float rs = rsqrtf(s2 * (1.f / 128.f) + 1e-5f);

    float4 g4 = ((const float4*)lng)[lane];
    float4 lb4 = ((const float4*)lnb)[lane];
    float4 o;
    o.x = fmaf(cx * rs, g4.x, lb4.x);
    o.y = fmaf(cy * rs, g4.y, lb4.y);
    o.z = fmaf(cz * rs, g4.z, lb4.z);
    o.w = fmaf(cw * rs, g4.w, lb4.w);
    ((float4*)hout)[n * 32 + lane] = o;
}

// ---------------- pooling + heads (deterministic, double accumulation) ------
__global__ void pool_partial(const float* __restrict__ hf) {  // grid 1024 x 128
    int col = threadIdx.x;
    int b = blockIdx.x;
    int r0 = b * 98;
    int r1 = min(NN, r0 + 98);
    double a = 0.0;
    for (int r = r0; r < r1; ++r) a += (double)hf[(long)r * 128 + col];
    g_part[b * 128 + col] = a;
}

__global__ void head_kernel(const float* __restrict__ Wmu,
                            const float* __restrict__ bmu,
                            const float* __restrict__ Wlv,
                            const float* __restrict__ blv,
                            float* __restrict__ out) {  // 1 block x 128
    __shared__ float p[128];
    int t = threadIdx.x;
    double s = 0.0;
    for (int b = 0; b < 1024; ++b) s += g_part[b * 128 + t];
    float pf = (float)(s / (double)NN);
    p[t] = pf;
    __syncthreads();
    float mu = bmu[t], lv = blv[t];
#pragma unroll 8
    for (int k = 0; k < 128; ++k) {
        float pk = p[k];
        mu = fmaf(pk, Wmu[t * 128 + k], mu);
        lv = fmaf(pk, Wlv[t * 128 + k], lv);
    }
    out[t] = mu;
    out[128 + t] = lv;
    out[256 + (long)NN * 128 + t] = pf;
}

// ---------------- launch -----------------------------------------------------
extern "C" void kernel_launch(void* const* d_in, const int* in_sizes, int n_in,
                              void* d_out, int out_size) {
    const float* x      = (const float*)d_in[0];
    const int*   ei     = (const int*)d_in[1];
    const float* W_in   = (const float*)d_in[2];
    const float* b_in   = (const float*)d_in[3];
    const float* gat_W  = (const float*)d_in[4];
    const float* attsrc = (const float*)d_in[5];
    const float* attdst = (const float*)d_in[6];
    const float* gat_b  = (const float*)d_in[7];
    const float* ln_g   = (const float*)d_in[8];
    const float* ln_b   = (const float*)d_in[9];
    const float* W_mu   = (const float*)d_in[10];
    const float* b_mu   = (const float*)d_in[11];
    const float* W_lv   = (const float*)d_in[12];
    const float* b_lv   = (const float*)d_in[13];
    float* out = (float*)d_out;

    void *p_h, *p_xh, *p_wti, *p_wtg;
    cudaGetSymbolAddress(&p_h, g_h);
    cudaGetSymbolAddress(&p_xh, g_xh);
    cudaGetSymbolAddress(&p_wti, g_Wt_in);
    cudaGetSymbolAddress(&p_wtg, g_Wt_gat);
    float* hbuf = (float*)p_h;
    float* xhbuf = (float*)p_xh;

    const int smem_bytes = (32 * 129 + 32 * 128) * 4;  // 32896
    cudaFuncSetAttribute(gemm_kernel<256, false>,
                         cudaFuncAttributeMaxDynamicSharedMemorySize, smem_bytes);
    cudaFuncSetAttribute(gemm_kernel<128, true>,
                         cudaFuncAttributeMaxDynamicSharedMemorySize, smem_bytes);

    const int gemm_grid = (NN + 127) / 128;  // 782

    // profiler captures launch #4 -> keep it the layer-0 GEMM.
    transpose_weights<<<775, 256>>>(W_in, gat_W);                       // 1
    gemm_kernel<256, false><<<gemm_grid, 256, smem_bytes>>>(            // 2
        x, (const float*)p_wti, b_in, hbuf, NN, nullptr, nullptr);
    hist_kernel<<<1024, 256>>>(ei + EE);                                // 3
    gemm_kernel<128, true><<<gemm_grid, 256, smem_bytes>>>(             // 4 (profiled)
        hbuf, (const float*)p_wtg, nullptr, xhbuf, NN,
        attsrc, attdst);
    scan_pass1<<<98, 1024>>>();                                         // 5
    scan_pass2<<<1, 128>>>();                                           // 6
    scan_pass3<<<98, 1024>>>();                                         // 7
    scatter_kernel<<<1024, 256>>>(ei, ei + EE);                         // 8

    for (int l = 0; l < 4; ++l) {
        if (l > 0) {
            gemm_kernel<128, true><<<gemm_grid, 256, smem_bytes>>>(
                hbuf, (const float*)p_wtg + l * 16384, nullptr, xhbuf, NN,
                attsrc + l * 128, attdst + l * 128);
        }
        aggregate_kernel<<<NN / 8, 256>>>(gat_b + l * 128, ln_g + l * 128,
                                          ln_b + l * 128,
                                          (l == 3) ? (out + 256) : hbuf);
    }

    pool_partial<<<1024, 128>>>(out + 256);
    head_kernel<<<1, 128>>>(W_mu, b_mu, W_lv, b_lv, out);
}

// round 6
// speedup vs baseline: 1.0312x; 1.0312x over previous
#include <cuda_runtime.h>
#include <string.h>

#define NN 100000
#define EE 1600000
#define DD 128
#define HH 8

typedef unsigned long long ull;

// ---------------- scratch (device globals; no allocations allowed) ----------
__device__ __align__(16) float g_h[NN * DD];     // current hidden state
__device__ __align__(16) float g_xh[NN * DD];    // per-layer transformed features
__device__ float g_es[NN * HH];                  // per-node src attention logits
__device__ float g_ed[NN * HH];                  // per-node dst attention logits
__device__ int   g_deg[NN];
__device__ int   g_off[NN + 1];
__device__ int   g_cur[NN];
__device__ int   g_csr[EE];                      // src ids grouped by dst
__device__ int   g_bsum[128];                    // scan block totals
__device__ int   g_boff[128];                    // scan block offsets
__device__ double g_part[1024 * DD];             // pooling partials
__device__ __align__(16) float g_Wt_in[256 * DD];    // W_in transposed [K=256][128]
__device__ __align__(16) float g_Wt_gat[4 * DD * DD];// gat_W transposed per layer

// ---------------- weight transpose + degree zeroing (one launch) ------------
__global__ void transpose_weights(const float* __restrict__ Win,
                                  const float* __restrict__ gw) {
    int idx = blockIdx.x * blockDim.x + threadIdx.x;
    if (idx < 256 * 128) {
        int n = idx & 127;
        int k = idx >> 7;                 // 0..255
        g_Wt_in[k * 128 + n] = Win[n * 256 + k];
    } else if (idx < 98304) {
        int r = idx - 256 * 128;          // 0..65535
        int n = r & 127;
        int t = r >> 7;
        int k = t & 127;
        int l = t >> 7;
        g_Wt_gat[l * 16384 + k * 128 + n] = gw[l * 16384 + n * 128 + k];
    } else if (idx - 98304 < NN) {
        g_deg[idx - 98304] = 0;
    }
}

__device__ __forceinline__ float2 unpack2(ull v) {
    float2 f;
    memcpy(&f, &v, 8);
    return f;
}

// ---------------- GEMM: C[M,128] = A[M,K] @ Wt[K,128] (+bias) ---------------
// BM=128, BN=128, BK=32. 256 threads, per-thread tile = 16 rows x 4 cols.
// Warp = 32 col-lanes (tx) x single row-group (ty): per warp-k the L1 traffic
// is 1 conflict-free LDS.128 (B) + 4 broadcast LDS.128 (A) = 8 wavefronts vs
// 32 FFMA2 -> L1 load is 25% of FMA demand. A smem stride 132 keeps 16B
// alignment for reads; B rows are contiguous so col-sliced LDS.128 is
// conflict-free. Optionally fuses attention logits into the epilogue.
template <int K, bool ATTN>
__global__ void __launch_bounds__(256, 2)
gemm_kernel(const float* __restrict__ A, const float* __restrict__ Wt,
            const float* __restrict__ bias, float* __restrict__ C, int M,
            const float* __restrict__ asrc, const float* __restrict__ adst) {
    constexpr int BM = 128, BN = 128, BK = 32;
    constexpr int AS = 132;  // %4==0 -> 16B-aligned rows; STS 4-way (load phase only)
    extern __shared__ float smem[];
    float* As = smem;            // [BK][AS]   (k-major, transposed store)
    float* Bs = smem + BK * AS;  // [BK][BN]

    int tid = threadIdx.x;
    int tx = tid & 31;   // col group: cols tx*4 .. tx*4+3
    int ty = tid >> 5;   // row group: rows ty*16 .. ty*16+15
    int row0 = blockIdx.x * BM;

    ull acc[16][2];  // 16 rows x {cols(0,1), cols(2,3)}
#pragma unroll
    for (int i = 0; i < 16; ++i) { acc[i][0] = 0ull; acc[i][1] = 0ull; }

    for (int kk = 0; kk < K; kk += BK) {
        // A tile 128x32: lane tx = k column (coalesced LDG), rows ty + 8i
#pragma unroll
        for (int i = 0; i < 16; ++i) {
            int m = ty + i * 8;
            int row = row0 + m;
            float v = (row < M) ? A[(long)row * K + kk + tx] : 0.f;
            As[tx * AS + m] = v;
        }
        // B tile 32x128 floats as float4: n4 = tx, k = ty + 8i
#pragma unroll
        for (int i = 0; i < 4; ++i) {
            int k = ty + i * 8;
            float4 v = *(const float4*)&Wt[(kk + k) * BN + tx * 4];
            *(float4*)&Bs[k * BN + tx * 4] = v;
        }
        __syncthreads();
#pragma unroll 8
        for (int k = 0; k < BK; ++k) {
            ulonglong2 b = *(const ulonglong2*)&Bs[k * BN + tx * 4];
            const float* arow = &As[k * AS + ty * 16];
            float4 a0 = *(const float4*)(arow);
            float4 a1 = *(const float4*)(arow + 4);
            float4 a2 = *(const float4*)(arow + 8);
            float4 a3 = *(const float4*)(arow + 12);
            float av[16] = {a0.x, a0.y, a0.z, a0.w, a1.x, a1.y, a1.z, a1.w,
                            a2.x, a2.y, a2.z, a2.w, a3.x, a3.y, a3.z, a3.w};
#pragma unroll
            for (int i = 0; i < 16; ++i) {
                ull ap;
                asm("mov.b64 %0, {%1, %1};" : "=l"(ap) : "f"(av[i]));
                asm("fma.rn.f32x2 %0, %1, %2, %0;"
                    : "+l"(acc[i][0]) : "l"(ap), "l"(b.x));
                asm("fma.rn.f32x2 %0, %1, %2, %0;"
                    : "+l"(acc[i][1]) : "l"(ap), "l"(b.y));
            }
        }
        __syncthreads();
    }

    float4 bv = make_float4(0.f, 0.f, 0.f, 0.f);
    if (bias) bv = *(const float4*)&bias[tx * 4];

    float4 as4, ad4;
    if (ATTN) {
        as4 = ((const float4*)asrc)[tx];
        ad4 = ((const float4*)adst)[tx];
    }

#pragma unroll
    for (int i = 0; i < 16; ++i) {
        int row = row0 + ty * 16 + i;
        float2 p01 = unpack2(acc[i][0]);
        float2 p23 = unpack2(acc[i][1]);
        float4 o;
        o.x = p01.x + bv.x;
        o.y = p01.y + bv.y;
        o.z = p23.x + bv.z;
        o.w = p23.y + bv.w;
        if (row < M) *(float4*)&C[(long)row * 128 + tx * 4] = o;
        if (ATTN) {
            // head = tx>>2; quad (tx&3) covers the head's 16 channels
            float s = o.x * as4.x + o.y * as4.y + o.z * as4.z + o.w * as4.w;
            float t = o.x * ad4.x + o.y * ad4.y + o.z * ad4.z + o.w * ad4.w;
            s += __shfl_xor_sync(0xffffffffu, s, 1);
            s += __shfl_xor_sync(0xffffffffu, s, 2);
            t += __shfl_xor_sync(0xffffffffu, t, 1);
            t += __shfl_xor_sync(0xffffffffu, t, 2);
            if (row < M && (tx & 3) == 0) {
                int h = tx >> 2;
                g_es[row * 8 + h] = s;
                g_ed[row * 8 + h] = t;
            }
        }
    }
}

// ---------------- CSR build --------------------------------------------------
__global__ void hist_kernel(const int* __restrict__ dst) {
    for (int i = blockIdx.x * blockDim.x + threadIdx.x; i < EE;
         i += gridDim.x * blockDim.x)
        atomicAdd(&g_deg[dst[i]], 1);
}

// multi-block exclusive scan: pass1 local scan, pass2 block sums, pass3 offsets
__global__ void scan_pass1() {  // grid 98, block 1024
    __shared__ int wsum[32];
    int tid = threadIdx.x, lane = tid & 31, wid = tid >> 5;
    int idx = blockIdx.x * 1024 + tid;
    int v = (idx < NN) ? g_deg[idx] : 0;
    int x = v;
#pragma unroll
    for (int o = 1; o < 32; o <<= 1) {
        int t = __shfl_up_sync(0xffffffffu, x, o);
        if (lane >= o) x += t;
    }
    if (lane == 31) wsum[wid] = x;
    __syncthreads();
    if (wid == 0) {
        int y = wsum[lane];
#pragma unroll
        for (int o = 1; o < 32; o <<= 1) {
            int t = __shfl_up_sync(0xffffffffu, y, o);
            if (lane >= o) y += t;
        }
        wsum[lane] = y;
    }
    __syncthreads();
    int pre = (wid > 0) ? wsum[wid - 1] : 0;
    int incl = pre + x;
    if (idx < NN) g_off[idx] = incl - v;   // block-local exclusive
    if (tid == 1023) g_bsum[blockIdx.x] = incl;
}

__global__ void scan_pass2() {  // 1 block, 128 threads (>= 98 block sums)
    __shared__ int wsum[4];
    int tid = threadIdx.x, lane = tid & 31, wid = tid >> 5;
    int v = (tid < 98) ? g_bsum[tid] : 0;
    int x = v;
#pragma unroll
    for (int o = 1; o < 32; o <<= 1) {
        int t = __shfl_up_sync(0xffffffffu, x, o);
        if (lane >= o) x += t;
    }
    if (lane == 31) wsum[wid] = x;
    __syncthreads();
    if (tid == 0) {
        int a = 0;
#pragma unroll
        for (int i = 0; i < 4; ++i) { int t = wsum[i]; wsum[i] = a; a += t; }
    }
    __syncthreads();
    int incl = wsum[wid] + x;
    if (tid < 98) g_boff[tid] = incl - v;
    if (tid == 127) g_off[NN] = incl;
}

__global__ void scan_pass3() {  // grid 98, block 1024
    int idx = blockIdx.x * 1024 + threadIdx.x;
    if (idx < NN) {
        int o = g_off[idx] + g_boff[blockIdx.x];
        g_off[idx] = o;
        g_cur[idx] = o;
    }
}

__global__ void scatter_kernel(const int* __restrict__ src,
                               const int* __restrict__ dst) {
    for (int i = blockIdx.x * blockDim.x + threadIdx.x; i < EE;
         i += gridDim.x * blockDim.x) {
        int d = dst[i];
        int p = atomicAdd(&g_cur[d], 1);
        g_csr[p] = src[i];
    }
}

// ---------------- fused aggregate + residual + LayerNorm --------------------
// one warp per dst node; lane owns channels [4*lane, 4*lane+4); head = lane/4.
// Softmax without max-shift (logits are provably tiny here; shift-invariant).
__global__ void __launch_bounds__(256)
aggregate_kernel(const float* __restrict__ gbias, const float* __restrict__ lng,
                 const float* __restrict__ lnb, float* __restrict__ hout) {
    int lane = threadIdx.x & 31;
    int n = blockIdx.x * 8 + (threadIdx.x >> 5);
    int head = lane >> 2;
    const float4* xh4 = (const float4*)g_xh;

    float edn = g_ed[n * 8 + head];
    float e0 = g_es[n * 8 + head] + edn;
    e0 = (e0 > 0.f) ? e0 : 0.2f * e0;
    float w0 = __expf(e0);

    float d = w0;
    float4 sv = xh4[n * 32 + lane];
    float4 acc;
    acc.x = w0 * sv.x; acc.y = w0 * sv.y; acc.z = w0 * sv.z; acc.w = w0 * sv.w;

    int beg = g_off[n], end = g_off[n + 1];
#pragma unroll 4
    for (int j = beg; j < end; ++j) {
        int s = g_csr[j];
        float e = __ldg(&g_es[s * 8 + head]) + edn;
        e = (e > 0.f) ? e : 0.2f * e;
        float w = __expf(e);
        float4 v = xh4[s * 32 + lane];
        acc.x = fmaf(w, v.x, acc.x);
        acc.y = fmaf(w, v.y, acc.y);
        acc.z = fmaf(w, v.z, acc.z);
        acc.w = fmaf(w, v.w, acc.w);
        d += w;
    }
    float invd = 1.f / (d + 1e-16f);

    const float4* hin4 = (const float4*)g_h;
    float4 h0 = hin4[n * 32 + lane];
    float4 b4 = ((const float4*)gbias)[lane];
    float4 v;
    v.x = h0.x + acc.x * invd + b4.x;
    v.y = h0.y + acc.y * invd + b4.y;
    v.z = h0.z + acc.z * invd + b4.z;
    v.w = h0.w + acc.w * invd + b4.w;

    // LayerNorm across the warp's 128 values
    float s1 = v.x + v.y + v.z + v.w;
#pragma unroll
    for (int o = 16; o; o >>= 1) s1 += __shfl_xor_sync(0xffffffffu, s1, o);
    float mean = s1 * (1.f / 128.f);
    float cx = v.x - mean, cy = v.y - mean, cz = v.z - mean, cw = v.w - mean;
    float s2 = cx * cx + cy * cy + cz * cz + cw * cw;
#pragma unroll
    for (int o = 16; o; o >>= 1) s2 += __shfl_xor_sync(0xffffffffu, s2, o);
    float rs = rsqrtf(s2 * (1.f / 128.f) + 1e-5f);

    float4 g4 = ((const float4*)lng)[lane];
    float4 lb4 = ((const float4*)lnb)[lane];
    float4 o;
    o.x = fmaf(cx * rs, g4.x, lb4.x);
    o.y = fmaf(cy * rs, g4.y, lb4.y);
    o.z = fmaf(cz * rs, g4.z, lb4.z);
    o.w = fmaf(cw * rs, g4.w, lb4.w);
    ((float4*)hout)[n * 32 + lane] = o;
}

// ---------------- pooling + heads (deterministic, double accumulation) ------
__global__ void pool_partial(const float* __restrict__ hf) {  // grid 1024 x 128
    int col = threadIdx.x;
    int b = blockIdx.x;
    int r0 = b * 98;
    int r1 = min(NN, r0 + 98);
    double a = 0.0;
    for (int r = r0; r < r1; ++r) a += (double)hf[(long)r * 128 + col];
    g_part[b * 128 + col] = a;
}

__global__ void head_kernel(const float* __restrict__ Wmu,
                            const float* __restrict__ bmu,
                            const float* __restrict__ Wlv,
                            const float* __restrict__ blv,
                            float* __restrict__ out) {  // 1 block x 128
    __shared__ float p[128];
    int t = threadIdx.x;
    double s = 0.0;
    for (int b = 0; b < 1024; ++b) s += g_part[b * 128 + t];
    float pf = (float)(s / (double)NN);
    p[t] = pf;
    __syncthreads();
    float mu = bmu[t], lv = blv[t];
#pragma unroll 8
    for (int k = 0; k < 128; ++k) {
        float pk = p[k];
        mu = fmaf(pk, Wmu[t * 128 + k], mu);
        lv = fmaf(pk, Wlv[t * 128 + k], lv);
    }
    out[t] = mu;
    out[128 + t] = lv;
    out[256 + (long)NN * 128 + t] = pf;
}

// ---------------- launch -----------------------------------------------------
extern "C" void kernel_launch(void* const* d_in, const int* in_sizes, int n_in,
                              void* d_out, int out_size) {
    const float* x      = (const float*)d_in[0];
    const int*   ei     = (const int*)d_in[1];
    const float* W_in   = (const float*)d_in[2];
    const float* b_in   = (const float*)d_in[3];
    const float* gat_W  = (const float*)d_in[4];
    const float* attsrc = (const float*)d_in[5];
    const float* attdst = (const float*)d_in[6];
    const float* gat_b  = (const float*)d_in[7];
    const float* ln_g   = (const float*)d_in[8];
    const float* ln_b   = (const float*)d_in[9];
    const float* W_mu   = (const float*)d_in[10];
    const float* b_mu   = (const float*)d_in[11];
    const float* W_lv   = (const float*)d_in[12];
    const float* b_lv   = (const float*)d_in[13];
    float* out = (float*)d_out;

    void *p_h, *p_xh, *p_wti, *p_wtg;
    cudaGetSymbolAddress(&p_h, g_h);
    cudaGetSymbolAddress(&p_xh, g_xh);
    cudaGetSymbolAddress(&p_wti, g_Wt_in);
    cudaGetSymbolAddress(&p_wtg, g_Wt_gat);
    float* hbuf = (float*)p_h;
    float* xhbuf = (float*)p_xh;

    const int smem_bytes = (32 * 132 + 32 * 128) * 4;  // 33280
    cudaFuncSetAttribute(gemm_kernel<256, false>,
                         cudaFuncAttributeMaxDynamicSharedMemorySize, smem_bytes);
    cudaFuncSetAttribute(gemm_kernel<128, true>,
                         cudaFuncAttributeMaxDynamicSharedMemorySize, smem_bytes);

    const int gemm_grid = (NN + 127) / 128;  // 782

    // profiler captures launch #4 -> keep it the layer-0 GEMM.
    transpose_weights<<<775, 256>>>(W_in, gat_W);                       // 1
    gemm_kernel<256, false><<<gemm_grid, 256, smem_bytes>>>(            // 2
        x, (const float*)p_wti, b_in, hbuf, NN, nullptr, nullptr);
    hist_kernel<<<1024, 256>>>(ei + EE);                                // 3
    gemm_kernel<128, true><<<gemm_grid, 256, smem_bytes>>>(             // 4 (profiled)
        hbuf, (const float*)p_wtg, nullptr, xhbuf, NN,
        attsrc, attdst);
    scan_pass1<<<98, 1024>>>();                                         // 5
    scan_pass2<<<1, 128>>>();                                           // 6
    scan_pass3<<<98, 1024>>>();                                         // 7
    scatter_kernel<<<1024, 256>>>(ei, ei + EE);                         // 8

    for (int l = 0; l < 4; ++l) {
        if (l > 0) {
            gemm_kernel<128, true><<<gemm_grid, 256, smem_bytes>>>(
                hbuf, (const float*)p_wtg + l * 16384, nullptr, xhbuf, NN,
                attsrc + l * 128, attdst + l * 128);
        }
        aggregate_kernel<<<NN / 8, 256>>>(gat_b + l * 128, ln_g + l * 128,
                                          ln_b + l * 128,
                                          (l == 3) ? (out + 256) : hbuf);
    }

    pool_partial<<<1024, 128>>>(out + 256);
    head_kernel<<<1, 128>>>(W_mu, b_mu, W_lv, b_lv, out);
}

// round 7
// speedup vs baseline: 1.1190x; 1.0852x over previous
#include <cuda_runtime.h>
#include <cuda_fp16.h>
#include <string.h>

#define NN 100000
#define EE 1600000
#define DD 128
#define HH 8

typedef unsigned long long ull;

// ---------------- scratch (device globals; no allocations allowed) ----------
__device__ __align__(16) float  g_h[NN * DD];    // current hidden state
__device__ __align__(16) __half g_xhh[NN * DD];  // per-layer transformed feats (fp16)
__device__ float g_es[NN * HH];                  // per-node src attention logits
__device__ float g_ed[NN * HH];                  // per-node dst attention logits
__device__ int   g_deg[NN];
__device__ int   g_off[NN + 1];
__device__ int   g_cur[NN];
__device__ int   g_csr[EE];                      // src ids grouped by dst
__device__ int   g_bsum[128];                    // scan block totals
__device__ int   g_boff[128];                    // scan block offsets
__device__ double g_part[1024 * DD];             // pooling partials
__device__ __align__(16) float g_Wt_in[256 * DD];    // W_in transposed [K=256][128]
__device__ __align__(16) float g_Wt_gat[4 * DD * DD];// gat_W transposed per layer

// ---------------- weight transpose + degree zeroing (one launch) ------------
__global__ void transpose_weights(const float* __restrict__ Win,
                                  const float* __restrict__ gw) {
    int idx = blockIdx.x * blockDim.x + threadIdx.x;
    if (idx < 256 * 128) {
        int n = idx & 127;
        int k = idx >> 7;                 // 0..255
        g_Wt_in[k * 128 + n] = Win[n * 256 + k];
    } else if (idx < 98304) {
        int r = idx - 256 * 128;          // 0..65535
        int n = r & 127;
        int t = r >> 7;
        int k = t & 127;
        int l = t >> 7;
        g_Wt_gat[l * 16384 + k * 128 + n] = gw[l * 16384 + n * 128 + k];
    } else if (idx - 98304 < NN) {
        g_deg[idx - 98304] = 0;
    }
}

__device__ __forceinline__ float2 unpack2(ull v) {
    float2 f;
    memcpy(&f, &v, 8);
    return f;
}

// ---------------- GEMM: C[M,128] = A[M,K] @ Wt[K,128] (+bias) ---------------
// BM=64, BN=128, BK=64. 256 threads, 8x4 tile, packed fp32x2 FMA (R4 shape —
// best measured: 85.5us, fma 55%, occ 34%). When ATTN: writes fp16 xh + the
// per-head attention logits instead of the fp32 C matrix.
template <int K, bool ATTN>
__global__ void __launch_bounds__(256, 3)
gemm_kernel(const float* __restrict__ A, const float* __restrict__ Wt,
            const float* __restrict__ bias, float* __restrict__ C, int M,
            const float* __restrict__ asrc, const float* __restrict__ adst) {
    constexpr int BM = 64, BN = 128, BK = 64;
    constexpr int AS = BM + 4;  // pad=4 -> rows stay 16B aligned
    extern __shared__ float smem[];
    float* As = smem;            // [BK][AS]
    float* Bs = smem + BK * AS;  // [BK][BN]

    int tid = threadIdx.x;
    int tx = tid & 31;   // col group: cols tx*4 .. tx*4+3
    int ty = tid >> 5;   // row group: rows ty*8 .. ty*8+7
    int row0 = blockIdx.x * BM;

    ull acc[8][2];  // 8 rows x {cols(0,1), cols(2,3)} packed fp32 pairs
#pragma unroll
    for (int i = 0; i < 8; ++i) { acc[i][0] = 0ull; acc[i][1] = 0ull; }

    for (int kk = 0; kk < K; kk += BK) {
        // load A tile (scalar, coalesced along k), store transposed to As[k][m]
#pragma unroll
        for (int i = 0; i < (BM * BK) / 256; ++i) {
            int lin = tid + i * 256;
            int k = lin & (BK - 1);
            int m = lin >> 6;
            int row = row0 + m;
            float v = (row < M) ? A[(long)row * K + kk + k] : 0.f;
            As[k * AS + m] = v;
        }
        // load B tile: Wt is already k-major -> straight float4 copy
#pragma unroll
        for (int i = 0; i < (BK * BN) / (256 * 4); ++i) {
            int lin = tid + i * 256;
            int n4 = lin & 31;
            int k = lin >> 5;
            float4 v = *(const float4*)&Wt[(kk + k) * BN + n4 * 4];
            *(float4*)&Bs[k * BN + n4 * 4] = v;
        }
        __syncthreads();
#pragma unroll 8
        for (int k = 0; k < BK; ++k) {
            ull b01 = *(const ull*)&Bs[k * BN + tx * 4];
            ull b23 = *(const ull*)&Bs[k * BN + tx * 4 + 2];
            float4 a0 = *(const float4*)&As[k * AS + ty * 8];
            float4 a1 = *(const float4*)&As[k * AS + ty * 8 + 4];
            float av[8] = {a0.x, a0.y, a0.z, a0.w, a1.x, a1.y, a1.z, a1.w};
#pragma unroll
            for (int i = 0; i < 8; ++i) {
                ull ap;
                asm("mov.b64 %0, {%1, %1};" : "=l"(ap) : "f"(av[i]));
                asm("fma.rn.f32x2 %0, %1, %2, %0;"
                    : "+l"(acc[i][0]) : "l"(ap), "l"(b01));
                asm("fma.rn.f32x2 %0, %1, %2, %0;"
                    : "+l"(acc[i][1]) : "l"(ap), "l"(b23));
            }
        }
        __syncthreads();
    }

    float4 bv = make_float4(0.f, 0.f, 0.f, 0.f);
    if (bias) bv = *(const float4*)&bias[tx * 4];

    float4 as4, ad4;
    if (ATTN) {
        as4 = ((const float4*)asrc)[tx];
        ad4 = ((const float4*)adst)[tx];
    }

#pragma unroll
    for (int i = 0; i < 8; ++i) {
        int row = row0 + ty * 8 + i;
        float2 p01 = unpack2(acc[i][0]);
        float2 p23 = unpack2(acc[i][1]);
        float4 o;
        o.x = p01.x + bv.x;
        o.y = p01.y + bv.y;
        o.z = p23.x + bv.z;
        o.w = p23.y + bv.w;
        if (!ATTN) {
            if (row < M) *(float4*)&C[(long)row * 128 + tx * 4] = o;
        } else {
            if (row < M) {
                // fp16 xh for the gather-heavy aggregate (halves L2 traffic)
                __half2 ph0 = __floats2half2_rn(o.x, o.y);
                __half2 ph1 = __floats2half2_rn(o.z, o.w);
                uint2 u;
                memcpy(&u.x, &ph0, 4);
                memcpy(&u.y, &ph1, 4);
                *(uint2*)&g_xhh[(long)row * 128 + tx * 4] = u;
            }
            // head = tx>>2; quad (tx&3) covers the head's 16 channels
            float s = o.x * as4.x + o.y * as4.y + o.z * as4.z + o.w * as4.w;
            float t = o.x * ad4.x + o.y * ad4.y + o.z * ad4.z + o.w * ad4.w;
            s += __shfl_xor_sync(0xffffffffu, s, 1);
            s += __shfl_xor_sync(0xffffffffu, s, 2);
            t += __shfl_xor_sync(0xffffffffu, t, 1);
            t += __shfl_xor_sync(0xffffffffu, t, 2);
            if (row < M && (tx & 3) == 0) {
                int h = tx >> 2;
                g_es[row * 8 + h] = s;
                g_ed[row * 8 + h] = t;
            }
        }
    }
}

// ---------------- CSR build --------------------------------------------------
__global__ void hist_kernel(const int* __restrict__ dst) {
    for (int i = blockIdx.x * blockDim.x + threadIdx.x; i < EE;
         i += gridDim.x * blockDim.x)
        atomicAdd(&g_deg[dst[i]], 1);
}

// multi-block exclusive scan: pass1 local scan, pass2 block sums, pass3 offsets
__global__ void scan_pass1() {  // grid 98, block 1024
    __shared__ int wsum[32];
    int tid = threadIdx.x, lane = tid & 31, wid = tid >> 5;
    int idx = blockIdx.x * 1024 + tid;
    int v = (idx < NN) ? g_deg[idx] : 0;
    int x = v;
#pragma unroll
    for (int o = 1; o < 32; o <<= 1) {
        int t = __shfl_up_sync(0xffffffffu, x, o);
        if (lane >= o) x += t;
    }
    if (lane == 31) wsum[wid] = x;
    __syncthreads();
    if (wid == 0) {
        int y = wsum[lane];
#pragma unroll
        for (int o = 1; o < 32; o <<= 1) {
            int t = __shfl_up_sync(0xffffffffu, y, o);
            if (lane >= o) y += t;
        }
        wsum[lane] = y;
    }
    __syncthreads();
    int pre = (wid > 0) ? wsum[wid - 1] : 0;
    int incl = pre + x;
    if (idx < NN) g_off[idx] = incl - v;   // block-local exclusive
    if (tid == 1023) g_bsum[blockIdx.x] = incl;
}

__global__ void scan_pass2() {  // 1 block, 128 threads (>= 98 block sums)
    __shared__ int wsum[4];
    int tid = threadIdx.x, lane = tid & 31, wid = tid >> 5;
    int v = (tid < 98) ? g_bsum[tid] : 0;
    int x = v;
#pragma unroll
    for (int o = 1; o < 32; o <<= 1) {
        int t = __shfl_up_sync(0xffffffffu, x, o);
        if (lane >= o) x += t;
    }
    if (lane == 31) wsum[wid] = x;
    __syncthreads();
    if (tid == 0) {
        int a = 0;
#pragma unroll
        for (int i = 0; i < 4; ++i) { int t = wsum[i]; wsum[i] = a; a += t; }
    }
    __syncthreads();
    int incl = wsum[wid] + x;
    if (tid < 98) g_boff[tid] = incl - v;
    if (tid == 127) g_off[NN] = incl;
}

__global__ void scan_pass3() {  // grid 98, block 1024
    int idx = blockIdx.x * 1024 + threadIdx.x;
    if (idx < NN) {
        int o = g_off[idx] + g_boff[blockIdx.x];
        g_off[idx] = o;
        g_cur[idx] = o;
    }
}

__global__ void scatter_kernel(const int* __restrict__ src,
                               const int* __restrict__ dst) {
    for (int i = blockIdx.x * blockDim.x + threadIdx.x; i < EE;
         i += gridDim.x * blockDim.x) {
        int d = dst[i];
        int p = atomicAdd(&g_cur[d], 1);
        g_csr[p] = src[i];
    }
}

// ---------------- fused aggregate + residual + LayerNorm --------------------
// one warp per dst node; lane owns channels [4*lane, 4*lane+4); head = lane/4.
// Softmax without max-shift (logits are provably tiny; shift-invariant).
// Gathers xh rows in fp16 (256B/row/warp) to halve L2 traffic.
__global__ void __launch_bounds__(256)
aggregate_kernel(const float* __restrict__ gbias, const float* __restrict__ lng,
                 const float* __restrict__ lnb, float* __restrict__ hout) {
    int lane = threadIdx.x & 31;
    int n = blockIdx.x * 8 + (threadIdx.x >> 5);
    int head = lane >> 2;

    float edn = g_ed[n * 8 + head];
    float e0 = g_es[n * 8 + head] + edn;
    e0 = (e0 > 0.f) ? e0 : 0.2f * e0;
    float w0 = __expf(e0);

    float d = w0;
    uint2 hv0 = *(const uint2*)&g_xhh[(long)n * 128 + lane * 4];
    __half2 q0, q1;
    memcpy(&q0, &hv0.x, 4);
    memcpy(&q1, &hv0.y, 4);
    float2 f0 = __half22float2(q0);
    float2 f1 = __half22float2(q1);
    float4 acc;
    acc.x = w0 * f0.x; acc.y = w0 * f0.y; acc.z = w0 * f1.x; acc.w = w0 * f1.y;

    int beg = g_off[n], end = g_off[n + 1];
#pragma unroll 4
    for (int j = beg; j < end; ++j) {
        int s = g_csr[j];
        float e = __ldg(&g_es[s * 8 + head]) + edn;
        e = (e > 0.f) ? e : 0.2f * e;
        float w = __expf(e);
        uint2 hv = *(const uint2*)&g_xhh[(long)s * 128 + lane * 4];
        __half2 a0, a1;
        memcpy(&a0, &hv.x, 4);
        memcpy(&a1, &hv.y, 4);
        float2 v0 = __half22float2(a0);
        float2 v1 = __half22float2(a1);
        acc.x = fmaf(w, v0.x, acc.x);
        acc.y = fmaf(w, v0.y, acc.y);
        acc.z = fmaf(w, v1.x, acc.z);
        acc.w = fmaf(w, v1.y, acc.w);
        d += w;
    }
    float invd = 1.f / (d + 1e-16f);

    const float4* hin4 = (const float4*)g_h;
    float4 h0 = hin4[n * 32 + lane];
    float4 b4 = ((const float4*)gbias)[lane];
    float4 v;
    v.x = h0.x + acc.x * invd + b4.x;
    v.y = h0.y + acc.y * invd + b4.y;
    v.z = h0.z + acc.z * invd + b4.z;
    v.w = h0.w + acc.w * invd + b4.w;

    // LayerNorm across the warp's 128 values
    float s1 = v.x + v.y + v.z + v.w;
#pragma unroll
    for (int o = 16; o; o >>= 1) s1 += __shfl_xor_sync(0xffffffffu, s1, o);
    float mean = s1 * (1.f / 128.f);
    float cx = v.x - mean, cy = v.y - mean, cz = v.z - mean, cw = v.w - mean;
    float s2 = cx * cx + cy * cy + cz * cz + cw * cw;
#pragma unroll
    for (int o = 16; o; o >>= 1) s2 += __shfl_xor_sync(0xffffffffu, s2, o);
    float rs = rsqrtf(s2 * (1.f / 128.f) + 1e-5f);

    float4 g4 = ((const float4*)lng)[lane];
    float4 lb4 = ((const float4*)lnb)[lane];
    float4 o;
    o.x = fmaf(cx * rs, g4.x, lb4.x);
    o.y = fmaf(cy * rs, g4.y, lb4.y);
    o.z = fmaf(cz * rs, g4.z, lb4.z);
    o.w = fmaf(cw * rs, g4.w, lb4.w);
    ((float4*)hout)[n * 32 + lane] = o;
}

// ---------------- pooling + heads (deterministic, double accumulation) ------
__global__ void pool_partial(const float* __restrict__ hf) {  // grid 1024 x 128
    int col = threadIdx.x;
    int b = blockIdx.x;
    int r0 = b * 98;
    int r1 = min(NN, r0 + 98);
    double a = 0.0;
    for (int r = r0; r < r1; ++r) a += (double)hf[(long)r * 128 + col];
    g_part[b * 128 + col] = a;
}

__global__ void head_kernel(const float* __restrict__ Wmu,
                            const float* __restrict__ bmu,
                            const float* __restrict__ Wlv,
                            const float* __restrict__ blv,
                            float* __restrict__ out) {  // 1 block x 128
    __shared__ float p[128];
    int t = threadIdx.x;
    double s = 0.0;
    for (int b = 0; b < 1024; ++b) s += g_part[b * 128 + t];
    float pf = (float)(s / (double)NN);
    p[t] = pf;
    __syncthreads();
    float mu = bmu[t], lv = blv[t];
#pragma unroll 8
    for (int k = 0; k < 128; ++k) {
        float pk = p[k];
        mu = fmaf(pk, Wmu[t * 128 + k], mu);
        lv = fmaf(pk, Wlv[t * 128 + k], lv);
    }
    out[t] = mu;
    out[128 + t] = lv;
    out[256 + (long)NN * 128 + t] = pf;
}

// ---------------- launch -----------------------------------------------------
extern "C" void kernel_launch(void* const* d_in, const int* in_sizes, int n_in,
                              void* d_out, int out_size) {
    const float* x      = (const float*)d_in[0];
    const int*   ei     = (const int*)d_in[1];
    const float* W_in   = (const float*)d_in[2];
    const float* b_in   = (const float*)d_in[3];
    const float* gat_W  = (const float*)d_in[4];
    const float* attsrc = (const float*)d_in[5];
    const float* attdst = (const float*)d_in[6];
    const float* gat_b  = (const float*)d_in[7];
    const float* ln_g   = (const float*)d_in[8];
    const float* ln_b   = (const float*)d_in[9];
    const float* W_mu   = (const float*)d_in[10];
    const float* b_mu   = (const float*)d_in[11];
    const float* W_lv   = (const float*)d_in[12];
    const float* b_lv   = (const float*)d_in[13];
    float* out = (float*)d_out;

    void *p_h, *p_wti, *p_wtg;
    cudaGetSymbolAddress(&p_h, g_h);
    cudaGetSymbolAddress(&p_wti, g_Wt_in);
    cudaGetSymbolAddress(&p_wtg, g_Wt_gat);
    float* hbuf = (float*)p_h;

    const int smem_bytes = (64 * 68 + 64 * 128) * 4;  // 50176
    cudaFuncSetAttribute(gemm_kernel<256, false>,
                         cudaFuncAttributeMaxDynamicSharedMemorySize, smem_bytes);
    cudaFuncSetAttribute(gemm_kernel<128, true>,
                         cudaFuncAttributeMaxDynamicSharedMemorySize, smem_bytes);

    const int gemm_grid = (NN + 63) / 64;  // 1563

    // profiler captures launch #4 -> keep it the layer-0 GEMM.
    transpose_weights<<<775, 256>>>(W_in, gat_W);                       // 1
    gemm_kernel<256, false><<<gemm_grid, 256, smem_bytes>>>(            // 2
        x, (const float*)p_wti, b_in, hbuf, NN, nullptr, nullptr);
    hist_kernel<<<1024, 256>>>(ei + EE);                                // 3
    gemm_kernel<128, true><<<gemm_grid, 256, smem_bytes>>>(             // 4 (profiled)
        hbuf, (const float*)p_wtg, nullptr, nullptr, NN,
        attsrc, attdst);
    scan_pass1<<<98, 1024>>>();                                         // 5
    scan_pass2<<<1, 128>>>();                                           // 6
    scan_pass3<<<98, 1024>>>();                                         // 7
    scatter_kernel<<<1024, 256>>>(ei, ei + EE);                         // 8

    for (int l = 0; l < 4; ++l) {
        if (l > 0) {
            gemm_kernel<128, true><<<gemm_grid, 256, smem_bytes>>>(
                hbuf, (const float*)p_wtg + l * 16384, nullptr, nullptr, NN,
                attsrc + l * 128, attdst + l * 128);
        }
        aggregate_kernel<<<NN / 8, 256>>>(gat_b + l * 128, ln_g + l * 128,
                                          ln_b + l * 128,
                                          (l == 3) ? (out + 256) : hbuf);
    }

    pool_partial<<<1024, 128>>>(out + 256);
    head_kernel<<<1, 128>>>(W_mu, b_mu, W_lv, b_lv, out);
}

// round 10
// speedup vs baseline: 1.4642x; 1.3084x over previous
#include <cuda_runtime.h>
#include <cuda_fp16.h>
#include <string.h>
#include <stdint.h>

#define NN 100000
#define EE 1600000
#define DD 128
#define HH 8

typedef unsigned long long ull;

// ---------------- scratch (device globals; no allocations allowed) ----------
__device__ __align__(16) float  g_h[NN * DD];    // hidden state fp32 (residual)
__device__ __align__(16) __half g_hh[NN * DD];   // hidden state fp16 (MMA input)
__device__ __align__(16) __half g_xhh[NN * DD];  // transformed feats fp16
__device__ float g_es[NN * HH];
__device__ float g_ed[NN * HH];
__device__ int   g_deg[NN];
__device__ int   g_off[NN + 1];
__device__ int   g_cur[NN];
__device__ int   g_csr[EE];
__device__ int   g_bsum[128];
__device__ int   g_boff[128];
__device__ double g_part[1024 * DD];
__device__ __align__(16) float  g_Wt_in[256 * DD];   // W_in^T fp32 [K=256][128]
__device__ __align__(16) __half g_Wh[4 * DD * DD];   // gat_W fp16 [l][n][k] (as-is)

// single dynamic-smem symbol shared by all kernels
extern __shared__ char dynsmem[];

__device__ __forceinline__ uint32_t smem_u32(const void* p) {
    uint32_t a;
    asm("{ .reg .u64 t; cvta.to.shared.u64 t, %1; cvt.u32.u64 %0, t; }"
        : "=r"(a) : "l"(p));
    return a;
}

// ---------------- weight prep + degree zeroing -------------------------------
__global__ void transpose_weights(const float* __restrict__ Win,
                                  const float* __restrict__ gw) {
    int idx = blockIdx.x * blockDim.x + threadIdx.x;
    if (idx < 256 * 128) {
        int n = idx & 127;
        int k = idx >> 7;
        g_Wt_in[k * 128 + n] = Win[n * 256 + k];
    } else if (idx < 98304) {
        int r = idx - 32768;                 // [l][n][k] direct fp16 convert
        g_Wh[r] = __float2half(gw[r]);
    } else if (idx - 98304 < NN) {
        g_deg[idx - 98304] = 0;
    }
}

__device__ __forceinline__ float2 unpack2(ull v) {
    float2 f;
    memcpy(&f, &v, 8);
    return f;
}

// ---------------- input GEMM (K=256, fp32 FFMA2; writes h fp32 + fp16) ------
__global__ void __launch_bounds__(256, 3)
gemm256_kernel(const float* __restrict__ A, const float* __restrict__ Wt,
               const float* __restrict__ bias, float* __restrict__ C, int M) {
    constexpr int BM = 64, BN = 128, BK = 64, K = 256;
    constexpr int AS = BM + 4;
    float* smem = (float*)dynsmem;
    float* As = smem;
    float* Bs = smem + BK * AS;

    int tid = threadIdx.x;
    int tx = tid & 31;
    int ty = tid >> 5;
    int row0 = blockIdx.x * BM;

    ull acc[8][2];
#pragma unroll
    for (int i = 0; i < 8; ++i) { acc[i][0] = 0ull; acc[i][1] = 0ull; }

    for (int kk = 0; kk < K; kk += BK) {
#pragma unroll
        for (int i = 0; i < (BM * BK) / 256; ++i) {
            int lin = tid + i * 256;
            int k = lin & (BK - 1);
            int m = lin >> 6;
            int row = row0 + m;
            float v = (row < M) ? A[(long)row * K + kk + k] : 0.f;
            As[k * AS + m] = v;
        }
#pragma unroll
        for (int i = 0; i < (BK * BN) / (256 * 4); ++i) {
            int lin = tid + i * 256;
            int n4 = lin & 31;
            int k = lin >> 5;
            float4 v = *(const float4*)&Wt[(kk + k) * BN + n4 * 4];
            *(float4*)&Bs[k * BN + n4 * 4] = v;
        }
        __syncthreads();
#pragma unroll 8
        for (int k = 0; k < BK; ++k) {
            ull b01 = *(const ull*)&Bs[k * BN + tx * 4];
            ull b23 = *(const ull*)&Bs[k * BN + tx * 4 + 2];
            float4 a0 = *(const float4*)&As[k * AS + ty * 8];
            float4 a1 = *(const float4*)&As[k * AS + ty * 8 + 4];
            float av[8] = {a0.x, a0.y, a0.z, a0.w, a1.x, a1.y, a1.z, a1.w};
#pragma unroll
            for (int i = 0; i < 8; ++i) {
                ull ap;
                asm("mov.b64 %0, {%1, %1};" : "=l"(ap) : "f"(av[i]));
                asm("fma.rn.f32x2 %0, %1, %2, %0;"
                    : "+l"(acc[i][0]) : "l"(ap), "l"(b01));
                asm("fma.rn.f32x2 %0, %1, %2, %0;"
                    : "+l"(acc[i][1]) : "l"(ap), "l"(b23));
            }
        }
        __syncthreads();
    }

    float4 bv = *(const float4*)&bias[tx * 4];
#pragma unroll
    for (int i = 0; i < 8; ++i) {
        int row = row0 + ty * 8 + i;
        if (row < M) {
            float2 p01 = unpack2(acc[i][0]);
            float2 p23 = unpack2(acc[i][1]);
            float4 o;
            o.x = p01.x + bv.x;
            o.y = p01.y + bv.y;
            o.z = p23.x + bv.z;
            o.w = p23.y + bv.w;
            *(float4*)&C[(long)row * 128 + tx * 4] = o;
            __half2 h0 = __floats2half2_rn(o.x, o.y);
            __half2 h1 = __floats2half2_rn(o.z, o.w);
            uint2 u;
            memcpy(&u.x, &h0, 4);
            memcpy(&u.y, &h1, 4);
            *(uint2*)&g_hh[(long)row * 128 + tx * 4] = u;
        }
    }
}

// ---------------- HMMA layer GEMM: xh = h @ W^T (+attn logits) --------------
// 128x128x128 per CTA, 8 warps x (16 rows x 128 cols), mma.m16n8k16 f16->f32.
// A = h rows fp16, B = W [n][k] fp16 (col-major kxn for row.col mma).
#define HS_A 0
#define HS_B 32768
#define HS_AS 65536
#define HS_AD 66048
#define HS_TOT 66560

__device__ __forceinline__ void ldsm_x4(uint32_t& r0, uint32_t& r1,
                                        uint32_t& r2, uint32_t& r3,
                                        uint32_t addr) {
    asm volatile(
        "ldmatrix.sync.aligned.m8n8.x4.shared.b16 {%0,%1,%2,%3}, [%4];"
        : "=r"(r0), "=r"(r1), "=r"(r2), "=r"(r3) : "r"(addr));
}

__device__ __forceinline__ void mma16816(float* c, uint32_t a0, uint32_t a1,
                                         uint32_t a2, uint32_t a3,
                                         uint32_t b0, uint32_t b1) {
    asm volatile(
        "mma.sync.aligned.m16n8k16.row.col.f32.f16.f16.f32 "
        "{%0,%1,%2,%3}, {%4,%5,%6,%7}, {%8,%9}, {%0,%1,%2,%3};"
        : "+f"(c[0]), "+f"(c[1]), "+f"(c[2]), "+f"(c[3])
        : "r"(a0), "r"(a1), "r"(a2), "r"(a3), "r"(b0), "r"(b1));
}

__global__ void __launch_bounds__(256, 2)
gemm_hmma_kernel(const __half* __restrict__ Ah, const __half* __restrict__ Bh,
                 const float* __restrict__ asrc, const float* __restrict__ adst) {
    char* smem = dynsmem;
    uint32_t sb = smem_u32(smem);
    int tid = threadIdx.x;
    int lane = tid & 31;
    int wid = tid >> 5;
    long row0 = (long)blockIdx.x * 128;

    // load A (128 h-rows) and B (weights) as fp16, 16B-chunk XOR swizzle
#pragma unroll
    for (int p = 0; p < 8; ++p) {
        int lin = p * 256 + tid;       // 0..2047 chunks
        int r = lin >> 4;              // row 0..127
        int c = lin & 15;              // 16B chunk 0..15
        int swc = c ^ (r & 7);
        long grow = row0 + r;
        uint4 va = make_uint4(0, 0, 0, 0);
        if (grow < NN) va = *(const uint4*)&Ah[grow * 128 + c * 8];
        *(uint4*)(smem + HS_A + r * 256 + swc * 16) = va;
        uint4 vb = *(const uint4*)&Bh[r * 128 + c * 8];
        *(uint4*)(smem + HS_B + r * 256 + swc * 16) = vb;
    }
    if (tid < 128) {
        ((float*)(smem + HS_AS))[tid] = asrc[tid];
        ((float*)(smem + HS_AD))[tid] = adst[tid];
    }
    __syncthreads();

    int m0 = wid * 16;
    float acc[16][4];
#pragma unroll
    for (int t = 0; t < 16; ++t)
#pragma unroll
        for (int i = 0; i < 4; ++i) acc[t][i] = 0.f;

    int l15 = lane & 15;
    int khalf = lane >> 4;
    int ar = m0 + l15;

#pragma unroll
    for (int ks = 0; ks < 8; ++ks) {
        int kc = ks * 2 + khalf;
        uint32_t a0, a1, a2, a3;
        ldsm_x4(a0, a1, a2, a3,
                sb + HS_A + ar * 256 + (kc ^ (ar & 7)) * 16);
#pragma unroll
        for (int j = 0; j < 8; ++j) {
            int br = j * 16 + l15;
            uint32_t b0, b1, b2, b3;
            ldsm_x4(b0, b1, b2, b3,
                    sb + HS_B + br * 256 + (kc ^ (br & 7)) * 16);
            mma16816(acc[2 * j], a0, a1, a2, a3, b0, b2);
            mma16816(acc[2 * j + 1], a0, a1, a2, a3, b1, b3);
        }
    }

    // epilogue: fp16 xh + per-head attention logits
    const float* s_as = (const float*)(smem + HS_AS);
    const float* s_ad = (const float*)(smem + HS_AD);
    int rlo = m0 + (lane >> 2);
    long glo = row0 + rlo;
    long ghi = glo + 8;
    bool vlo = (glo < NN), vhi = (ghi < NN);

    float eslo[8], edlo[8], eshi[8], edhi[8];
#pragma unroll
    for (int h = 0; h < 8; ++h) { eslo[h] = edlo[h] = eshi[h] = edhi[h] = 0.f; }

#pragma unroll
    for (int t = 0; t < 16; ++t) {
        int col = t * 8 + (lane & 3) * 2;
        int h = t >> 1;
        float c0 = acc[t][0], c1 = acc[t][1];
        float c2 = acc[t][2], c3 = acc[t][3];
        if (vlo) {
            __half2 lo2 = __floats2half2_rn(c0, c1);
            *(__half2*)&g_xhh[glo * 128 + col] = lo2;
        }
        if (vhi) {
            __half2 hi2 = __floats2half2_rn(c2, c3);
            *(__half2*)&g_xhh[ghi * 128 + col] = hi2;
        }
        float as0 = s_as[col], as1 = s_as[col + 1];
        float ad0 = s_ad[col], ad1 = s_ad[col + 1];
        eslo[h] += c0 * as0 + c1 * as1;
        edlo[h] += c0 * ad0 + c1 * ad1;
        eshi[h] += c2 * as0 + c3 * as1;
        edhi[h] += c2 * ad0 + c3 * ad1;
    }
#pragma unroll
    for (int h = 0; h < 8; ++h) {
        eslo[h] += __shfl_xor_sync(0xffffffffu, eslo[h], 1);
        eslo[h] += __shfl_xor_sync(0xffffffffu, eslo[h], 2);
        edlo[h] += __shfl_xor_sync(0xffffffffu, edlo[h], 1);
        edlo[h] += __shfl_xor_sync(0xffffffffu, edlo[h], 2);
        eshi[h] += __shfl_xor_sync(0xffffffffu, eshi[h], 1);
        eshi[h] += __shfl_xor_sync(0xffffffffu, eshi[h], 2);
        edhi[h] += __shfl_xor_sync(0xffffffffu, edhi[h], 1);
        edhi[h] += __shfl_xor_sync(0xffffffffu, edhi[h], 2);
    }
    if ((lane & 3) == 0) {
        if (vlo) {
            *(float4*)&g_es[glo * 8] = make_float4(eslo[0], eslo[1], eslo[2], eslo[3]);
            *(float4*)&g_es[glo * 8 + 4] = make_float4(eslo[4], eslo[5], eslo[6], eslo[7]);
            *(float4*)&g_ed[glo * 8] = make_float4(edlo[0], edlo[1], edlo[2], edlo[3]);
            *(float4*)&g_ed[glo * 8 + 4] = make_float4(edlo[4], edlo[5], edlo[6], edlo[7]);
        }
        if (vhi) {
            *(float4*)&g_es[ghi * 8] = make_float4(eshi[0], eshi[1], eshi[2], eshi[3]);
            *(float4*)&g_es[ghi * 8 + 4] = make_float4(eshi[4], eshi[5], eshi[6], eshi[7]);
            *(float4*)&g_ed[ghi * 8] = make_float4(edhi[0], edhi[1], edhi[2], edhi[3]);
            *(float4*)&g_ed[ghi * 8 + 4] = make_float4(edhi[4], edhi[5], edhi[6], edhi[7]);
        }
    }
}

// ---------------- CSR build --------------------------------------------------
__global__ void hist_kernel(const int* __restrict__ dst) {
    for (int i = blockIdx.x * blockDim.x + threadIdx.x; i < EE;
         i += gridDim.x * blockDim.x)
        atomicAdd(&g_deg[dst[i]], 1);
}

__global__ void scan_pass1() {  // grid 98, block 1024
    __shared__ int wsum[32];
    int tid = threadIdx.x, lane = tid & 31, wid = tid >> 5;
    int idx = blockIdx.x * 1024 + tid;
    int v = (idx < NN) ? g_deg[idx] : 0;
    int x = v;
#pragma unroll
    for (int o = 1; o < 32; o <<= 1) {
        int t = __shfl_up_sync(0xffffffffu, x, o);
        if (lane >= o) x += t;
    }
    if (lane == 31) wsum[wid] = x;
    __syncthreads();
    if (wid == 0) {
        int y = wsum[lane];
#pragma unroll
        for (int o = 1; o < 32; o <<= 1) {
            int t = __shfl_up_sync(0xffffffffu, y, o);
            if (lane >= o) y += t;
        }
        wsum[lane] = y;
    }
    __syncthreads();
    int pre = (wid > 0) ? wsum[wid - 1] : 0;
    int incl = pre + x;
    if (idx < NN) g_off[idx] = incl - v;
    if (tid == 1023) g_bsum[blockIdx.x] = incl;
}

__global__ void scan_pass2() {  // 1 block, 128 threads
    __shared__ int wsum[4];
    int tid = threadIdx.x, lane = tid & 31, wid = tid >> 5;
    int v = (tid < 98) ? g_bsum[tid] : 0;
    int x = v;
#pragma unroll
    for (int o = 1; o < 32; o <<= 1) {
        int t = __shfl_up_sync(0xffffffffu, x, o);
        if (lane >= o) x += t;
    }
    if (lane == 31) wsum[wid] = x;
    __syncthreads();
    if (tid == 0) {
        int a = 0;
#pragma unroll
        for (int i = 0; i < 4; ++i) { int t = wsum[i]; wsum[i] = a; a += t; }
    }
    __syncthreads();
    int incl = wsum[wid] + x;
    if (tid < 98) g_boff[tid] = incl - v;
    if (tid == 127) g_off[NN] = incl;
}

__global__ void scan_pass3() {  // grid 98, block 1024
    int idx = blockIdx.x * 1024 + threadIdx.x;
    if (idx < NN) {
        int o = g_off[idx] + g_boff[blockIdx.x];
        g_off[idx] = o;
        g_cur[idx] = o;
    }
}

__global__ void scatter_kernel(const int* __restrict__ src,
                               const int* __restrict__ dst) {
    for (int i = blockIdx.x * blockDim.x + threadIdx.x; i < EE;
         i += gridDim.x * blockDim.x) {
        int d = dst[i];
        int p = atomicAdd(&g_cur[d], 1);
        g_csr[p] = src[i];
    }
}

// ---------------- fused aggregate + residual + LayerNorm --------------------
__global__ void __launch_bounds__(256)
aggregate_kernel(const float* __restrict__ gbias, const float* __restrict__ lng,
                 const float* __restrict__ lnb, float* __restrict__ hout,
                 __half* __restrict__ hh) {
    int lane = threadIdx.x & 31;
    int n = blockIdx.x * 8 + (threadIdx.x >> 5);
    int head = lane >> 2;

    float edn = g_ed[n * 8 + head];
    float e0 = g_es[n * 8 + head] + edn;
    e0 = (e0 > 0.f) ? e0 : 0.2f * e0;
    float w0 = __expf(e0);

    float d = w0;
    uint2 hv0 = *(const uint2*)&g_xhh[(long)n * 128 + lane * 4];
    __half2 q0, q1;
    memcpy(&q0, &hv0.x, 4);
    memcpy(&q1, &hv0.y, 4);
    float2 f0 = __half22float2(q0);
    float2 f1 = __half22float2(q1);
    float4 acc;
    acc.x = w0 * f0.x; acc.y = w0 * f0.y; acc.z = w0 * f1.x; acc.w = w0 * f1.y;

    int beg = g_off[n], end = g_off[n + 1];
#pragma unroll 4
    for (int j = beg; j < end; ++j) {
        int s = g_csr[j];
        float e = __ldg(&g_es[s * 8 + head]) + edn;
        e = (e > 0.f) ? e : 0.2f * e;
        float w = __expf(e);
        uint2 hv = *(const uint2*)&g_xhh[(long)s * 128 + lane * 4];
        __half2 a0, a1;
        memcpy(&a0, &hv.x, 4);
        memcpy(&a1, &hv.y, 4);
        float2 v0 = __half22float2(a0);
        float2 v1 = __half22float2(a1);
        acc.x = fmaf(w, v0.x, acc.x);
        acc.y = fmaf(w, v0.y, acc.y);
        acc.z = fmaf(w, v1.x, acc.z);
        acc.w = fmaf(w, v1.y, acc.w);
        d += w;
    }
    float invd = 1.f / (d + 1e-16f);

    const float4* hin4 = (const float4*)g_h;
    float4 h0 = hin4[n * 32 + lane];
    float4 b4 = ((const float4*)gbias)[lane];
    float4 v;
    v.x = h0.x + acc.x * invd + b4.x;
    v.y = h0.y + acc.y * invd + b4.y;
    v.z = h0.z + acc.z * invd + b4.z;
    v.w = h0.w + acc.w * invd + b4.w;

    float s1 = v.x + v.y + v.z + v.w;
#pragma unroll
    for (int o = 16; o; o >>= 1) s1 += __shfl_xor_sync(0xffffffffu, s1, o);
    float mean = s1 * (1.f / 128.f);
    float cx = v.x - mean, cy = v.y - mean, cz = v.z - mean, cw = v.w - mean;
    float s2 = cx * cx + cy * cy + cz * cz + cw * cw;
#pragma unroll
    for (int o = 16; o; o >>= 1) s2 += __shfl_xor_sync(0xffffffffu, s2, o);
    float rs = rsqrtf(s2 * (1.f / 128.f) + 1e-5f);

    float4 g4 = ((const float4*)lng)[lane];
    float4 lb4 = ((const float4*)lnb)[lane];
    float4 o;
    o.x = fmaf(cx * rs, g4.x, lb4.x);
    o.y = fmaf(cy * rs, g4.y, lb4.y);
    o.z = fmaf(cz * rs, g4.z, lb4.z);
    o.w = fmaf(cw * rs, g4.w, lb4.w);
    ((float4*)hout)[n * 32 + lane] = o;
    if (hh) {
        __half2 ph0 = __floats2half2_rn(o.x, o.y);
        __half2 ph1 = __floats2half2_rn(o.z, o.w);
        uint2 u;
        memcpy(&u.x, &ph0, 4);
        memcpy(&u.y, &ph1, 4);
        *(uint2*)&hh[(long)n * 128 + lane * 4] = u;
    }
}

// ---------------- pooling + heads --------------------------------------------
__global__ void pool_partial(const float* __restrict__ hf) {
    int col = threadIdx.x;
    int b = blockIdx.x;
    int r0 = b * 98;
    int r1 = min(NN, r0 + 98);
    double a = 0.0;
    for (int r = r0; r < r1; ++r) a += (double)hf[(long)r * 128 + col];
    g_part[b * 128 + col] = a;
}

__global__ void head_kernel(const float* __restrict__ Wmu,
                            const float* __restrict__ bmu,
                            const float* __restrict__ Wlv,
                            const float* __restrict__ blv,
                            float* __restrict__ out) {
    __shared__ float p[128];
    int t = threadIdx.x;
    double s = 0.0;
    for (int b = 0; b < 1024; ++b) s += g_part[b * 128 + t];
    float pf = (float)(s / (double)NN);
    p[t] = pf;
    __syncthreads();
    float mu = bmu[t], lv = blv[t];
#pragma unroll 8
    for (int k = 0; k < 128; ++k) {
        float pk = p[k];
        mu = fmaf(pk, Wmu[t * 128 + k], mu);
        lv = fmaf(pk, Wlv[t * 128 + k], lv);
    }
    out[t] = mu;
    out[128 + t] = lv;
    out[256 + (long)NN * 128 + t] = pf;
}

// ---------------- launch -----------------------------------------------------
extern "C" void kernel_launch(void* const* d_in, const int* in_sizes, int n_in,
                              void* d_out, int out_size) {
    const float* x      = (const float*)d_in[0];
    const int*   ei     = (const int*)d_in[1];
    const float* W_in   = (const float*)d_in[2];
    const float* b_in   = (const float*)d_in[3];
    const float* gat_W  = (const float*)d_in[4];
    const float* attsrc = (const float*)d_in[5];
    const float* attdst = (const float*)d_in[6];
    const float* gat_b  = (const float*)d_in[7];
    const float* ln_g   = (const float*)d_in[8];
    const float* ln_b   = (const float*)d_in[9];
    const float* W_mu   = (const float*)d_in[10];
    const float* b_mu   = (const float*)d_in[11];
    const float* W_lv   = (const float*)d_in[12];
    const float* b_lv   = (const float*)d_in[13];
    float* out = (float*)d_out;

    void *p_h, *p_hh, *p_wti, *p_wh;
    cudaGetSymbolAddress(&p_h, g_h);
    cudaGetSymbolAddress(&p_hh, g_hh);
    cudaGetSymbolAddress(&p_wti, g_Wt_in);
    cudaGetSymbolAddress(&p_wh, g_Wh);
    float* hbuf = (float*)p_h;
    __half* hhbuf = (__half*)p_hh;
    const __half* whbuf = (const __half*)p_wh;

    const int smem256 = (64 * 68 + 64 * 128) * 4;  // 50176
    cudaFuncSetAttribute(gemm256_kernel,
                         cudaFuncAttributeMaxDynamicSharedMemorySize, smem256);
    cudaFuncSetAttribute(gemm_hmma_kernel,
                         cudaFuncAttributeMaxDynamicSharedMemorySize, HS_TOT);

    const int grid256 = (NN + 63) / 64;    // 1563
    const int gridtc = (NN + 127) / 128;   // 782

    // profiler captures launch #4 -> layer-0 HMMA GEMM.
    transpose_weights<<<775, 256>>>(W_in, gat_W);                       // 1
    gemm256_kernel<<<grid256, 256, smem256>>>(x, (const float*)p_wti,   // 2
                                              b_in, hbuf, NN);
    hist_kernel<<<1024, 256>>>(ei + EE);                                // 3
    gemm_hmma_kernel<<<gridtc, 256, HS_TOT>>>(hhbuf, whbuf,             // 4 (profiled)
                                              attsrc, attdst);
    scan_pass1<<<98, 1024>>>();                                         // 5
    scan_pass2<<<1, 128>>>();                                           // 6
    scan_pass3<<<98, 1024>>>();                                         // 7
    scatter_kernel<<<1024, 256>>>(ei, ei + EE);                         // 8

    for (int l = 0; l < 4; ++l) {
        if (l > 0) {
            gemm_hmma_kernel<<<gridtc, 256, HS_TOT>>>(
                hhbuf, whbuf + l * 16384, attsrc + l * 128, attdst + l * 128);
        }
        aggregate_kernel<<<NN / 8, 256>>>(gat_b + l * 128, ln_g + l * 128,
                                          ln_b + l * 128,
                                          (l == 3) ? (out + 256) : hbuf,
                                          (l == 3) ? nullptr : hhbuf);
    }

    pool_partial<<<1024, 128>>>(out + 256);
    head_kernel<<<1, 128>>>(W_mu, b_mu, W_lv, b_lv, out);
}

// round 12
// speedup vs baseline: 1.6967x; 1.1588x over previous
#include <cuda_runtime.h>
#include <cuda_fp16.h>
#include <string.h>
#include <stdint.h>

#define NN 100000
#define EE 1600000
#define DD 128
#define HH 8

typedef unsigned long long ull;

// ---------------- scratch (device globals; no allocations allowed) ----------
__device__ __align__(16) float  g_h[NN * DD];    // hidden state fp32 (residual)
__device__ __align__(16) __half g_hh[NN * DD];   // hidden state fp16 (MMA input)
__device__ __align__(16) __half g_xhh[NN * DD];  // transformed feats fp16
__device__ float g_es[NN * HH];
__device__ float g_ed[NN * HH];
__device__ int   g_deg[NN];
__device__ int   g_off[NN + 1];
__device__ int   g_cur[NN];
__device__ int   g_csr[EE];
__device__ int   g_bsum[128];
__device__ int   g_boff[128];
__device__ double g_part[1024 * DD];
__device__ __align__(16) __half g_Whin[DD * 256];    // W_in fp16 [n][k]
__device__ __align__(16) __half g_Wh[4 * DD * DD];   // gat_W fp16 [l][n][k]

// single dynamic-smem symbol shared by all kernels
extern __shared__ char dynsmem[];

__device__ __forceinline__ uint32_t smem_u32(const void* p) {
    uint32_t a;
    asm("{ .reg .u64 t; cvta.to.shared.u64 t, %1; cvt.u32.u64 %0, t; }"
        : "=r"(a) : "l"(p));
    return a;
}

// ---------------- weight fp16 convert + degree zeroing -----------------------
__global__ void transpose_weights(const float* __restrict__ Win,
                                  const float* __restrict__ gw) {
    int idx = blockIdx.x * blockDim.x + threadIdx.x;
    if (idx < 32768) {
        g_Whin[idx] = __float2half(Win[idx]);       // [n][k] as-is
    } else if (idx < 98304) {
        int r = idx - 32768;
        g_Wh[r] = __float2half(gw[r]);              // [l][n][k] as-is
    } else if (idx - 98304 < NN) {
        g_deg[idx - 98304] = 0;
    }
}

// ---------------- unified HMMA GEMM ------------------------------------------
// C[M,128] = A[M,K] @ B^T (B = [128 n][K k] fp16). 128x128 tile per CTA,
// 8 warps x (16 rows x 128 cols), mma.m16n8k16 f16->f32, K chunked by 128.
// AFP32: A is fp32 in gmem, converted to fp16 during the swizzled smem store;
//        epilogue adds bias, writes C fp32 + g_hh fp16.
// ATTN:  epilogue writes g_xhh fp16 + fused per-head attention logits.
#define HS_A 0
#define HS_B 32768
#define HS_AS 65536
#define HS_AD 66048
#define HS_TOT 66560

__device__ __forceinline__ void ldsm_x4(uint32_t& r0, uint32_t& r1,
                                        uint32_t& r2, uint32_t& r3,
                                        uint32_t addr) {
    asm volatile(
        "ldmatrix.sync.aligned.m8n8.x4.shared.b16 {%0,%1,%2,%3}, [%4];"
        : "=r"(r0), "=r"(r1), "=r"(r2), "=r"(r3) : "r"(addr));
}

__device__ __forceinline__ void mma16816(float* c, uint32_t a0, uint32_t a1,
                                         uint32_t a2, uint32_t a3,
                                         uint32_t b0, uint32_t b1) {
    asm volatile(
        "mma.sync.aligned.m16n8k16.row.col.f32.f16.f16.f32 "
        "{%0,%1,%2,%3}, {%4,%5,%6,%7}, {%8,%9}, {%0,%1,%2,%3};"
        : "+f"(c[0]), "+f"(c[1]), "+f"(c[2]), "+f"(c[3])
        : "r"(a0), "r"(a1), "r"(a2), "r"(a3), "r"(b0), "r"(b1));
}

template <int K, bool AFP32, bool ATTN>
__global__ void __launch_bounds__(256, 2)
gemm_hmma_kernel(const void* __restrict__ Asrc, const __half* __restrict__ Bh,
                 const float* __restrict__ bias, float* __restrict__ Cout,
                 const float* __restrict__ asrc, const float* __restrict__ adst) {
    char* smem = dynsmem;
    uint32_t sb = smem_u32(smem);
    int tid = threadIdx.x;
    int lane = tid & 31;
    int wid = tid >> 5;
    long row0 = (long)blockIdx.x * 128;

    int m0 = wid * 16;
    float acc[16][4];
#pragma unroll
    for (int t = 0; t < 16; ++t)
#pragma unroll
        for (int i = 0; i < 4; ++i) acc[t][i] = 0.f;

    int l15 = lane & 15;
    int khalf = lane >> 4;
    int ar = m0 + l15;

    for (int kk = 0; kk < K; kk += 128) {
        if (kk) __syncthreads();
        // stage A (rows of x or h) and B (weights) as fp16, 16B XOR swizzle
#pragma unroll
        for (int p = 0; p < 8; ++p) {
            int lin = p * 256 + tid;       // 0..2047 chunks
            int r = lin >> 4;              // row 0..127
            int c = lin & 15;              // 16B chunk 0..15
            int swc = c ^ (r & 7);
            long grow = row0 + r;
            uint4 va = make_uint4(0, 0, 0, 0);
            if (grow < NN) {
                if (AFP32) {
                    const float* ax = (const float*)Asrc + grow * K + kk + c * 8;
                    float4 f0 = *(const float4*)ax;
                    float4 f1 = *(const float4*)(ax + 4);
                    __half2 h0 = __floats2half2_rn(f0.x, f0.y);
                    __half2 h1 = __floats2half2_rn(f0.z, f0.w);
                    __half2 h2 = __floats2half2_rn(f1.x, f1.y);
                    __half2 h3 = __floats2half2_rn(f1.z, f1.w);
                    memcpy(&va.x, &h0, 4);
                    memcpy(&va.y, &h1, 4);
                    memcpy(&va.z, &h2, 4);
                    memcpy(&va.w, &h3, 4);
                } else {
                    va = *(const uint4*)((const __half*)Asrc + grow * 128 + c * 8);
                }
            }
            *(uint4*)(smem + HS_A + r * 256 + swc * 16) = va;
            uint4 vb = *(const uint4*)&Bh[(long)r * K + kk + c * 8];
            *(uint4*)(smem + HS_B + r * 256 + swc * 16) = vb;
        }
        if (kk == 0 && tid < 128) {
            if (ATTN) {
                ((float*)(smem + HS_AS))[tid] = asrc[tid];
                ((float*)(smem + HS_AD))[tid] = adst[tid];
            }
            if (AFP32) ((float*)(smem + HS_AS))[tid] = bias[tid];
        }
        __syncthreads();

#pragma unroll
        for (int ks = 0; ks < 8; ++ks) {
            int kc = ks * 2 + khalf;
            uint32_t a0, a1, a2, a3;
            ldsm_x4(a0, a1, a2, a3,
                    sb + HS_A + ar * 256 + (kc ^ (ar & 7)) * 16);
#pragma unroll
            for (int j = 0; j < 8; ++j) {
                int br = j * 16 + l15;
                uint32_t b0, b1, b2, b3;
                ldsm_x4(b0, b1, b2, b3,
                        sb + HS_B + br * 256 + (kc ^ (br & 7)) * 16);
                mma16816(acc[2 * j], a0, a1, a2, a3, b0, b2);
                mma16816(acc[2 * j + 1], a0, a1, a2, a3, b1, b3);
            }
        }
    }

    // epilogue
    int rlo = m0 + (lane >> 2);
    long glo = row0 + rlo;
    long ghi = glo + 8;
    bool vlo = (glo < NN), vhi = (ghi < NN);

    if (AFP32) {
        const float* sbias = (const float*)(smem + HS_AS);
#pragma unroll
        for (int t = 0; t < 16; ++t) {
            int col = t * 8 + (lane & 3) * 2;
            float b0 = sbias[col], b1 = sbias[col + 1];
            float c0 = acc[t][0] + b0, c1 = acc[t][1] + b1;
            float c2 = acc[t][2] + b0, c3 = acc[t][3] + b1;
            if (vlo) {
                *(float2*)&Cout[glo * 128 + col] = make_float2(c0, c1);
                *(__half2*)&g_hh[glo * 128 + col] = __floats2half2_rn(c0, c1);
            }
            if (vhi) {
                *(float2*)&Cout[ghi * 128 + col] = make_float2(c2, c3);
                *(__half2*)&g_hh[ghi * 128 + col] = __floats2half2_rn(c2, c3);
            }
        }
    }
    if (ATTN) {
        const float* s_as = (const float*)(smem + HS_AS);
        const float* s_ad = (const float*)(smem + HS_AD);
        float eslo[8], edlo[8], eshi[8], edhi[8];
#pragma unroll
        for (int h = 0; h < 8; ++h) { eslo[h] = edlo[h] = eshi[h] = edhi[h] = 0.f; }
#pragma unroll
        for (int t = 0; t < 16; ++t) {
            int col = t * 8 + (lane & 3) * 2;
            int h = t >> 1;
            float c0 = acc[t][0], c1 = acc[t][1];
            float c2 = acc[t][2], c3 = acc[t][3];
            if (vlo) *(__half2*)&g_xhh[glo * 128 + col] = __floats2half2_rn(c0, c1);
            if (vhi) *(__half2*)&g_xhh[ghi * 128 + col] = __floats2half2_rn(c2, c3);
            float as0 = s_as[col], as1 = s_as[col + 1];
            float ad0 = s_ad[col], ad1 = s_ad[col + 1];
            eslo[h] += c0 * as0 + c1 * as1;
            edlo[h] += c0 * ad0 + c1 * ad1;
            eshi[h] += c2 * as0 + c3 * as1;
            edhi[h] += c2 * ad0 + c3 * ad1;
        }
#pragma unroll
        for (int h = 0; h < 8; ++h) {
            eslo[h] += __shfl_xor_sync(0xffffffffu, eslo[h], 1);
            eslo[h] += __shfl_xor_sync(0xffffffffu, eslo[h], 2);
            edlo[h] += __shfl_xor_sync(0xffffffffu, edlo[h], 1);
            edlo[h] += __shfl_xor_sync(0xffffffffu, edlo[h], 2);
            eshi[h] += __shfl_xor_sync(0xffffffffu, eshi[h], 1);
            eshi[h] += __shfl_xor_sync(0xffffffffu, eshi[h], 2);
            edhi[h] += __shfl_xor_sync(0xffffffffu, edhi[h], 1);
            edhi[h] += __shfl_xor_sync(0xffffffffu, edhi[h], 2);
        }
        if ((lane & 3) == 0) {
            if (vlo) {
                *(float4*)&g_es[glo * 8] = make_float4(eslo[0], eslo[1], eslo[2], eslo[3]);
                *(float4*)&g_es[glo * 8 + 4] = make_float4(eslo[4], eslo[5], eslo[6], eslo[7]);
                *(float4*)&g_ed[glo * 8] = make_float4(edlo[0], edlo[1], edlo[2], edlo[3]);
                *(float4*)&g_ed[glo * 8 + 4] = make_float4(edlo[4], edlo[5], edlo[6], edlo[7]);
            }
            if (vhi) {
                *(float4*)&g_es[ghi * 8] = make_float4(eshi[0], eshi[1], eshi[2], eshi[3]);
                *(float4*)&g_es[ghi * 8 + 4] = make_float4(eshi[4], eshi[5], eshi[6], eshi[7]);
                *(float4*)&g_ed[ghi * 8] = make_float4(edhi[0], edhi[1], edhi[2], edhi[3]);
                *(float4*)&g_ed[ghi * 8 + 4] = make_float4(edhi[4], edhi[5], edhi[6], edhi[7]);
            }
        }
    }
}

// ---------------- CSR build --------------------------------------------------
__global__ void hist_kernel(const int* __restrict__ dst) {
    for (int i = blockIdx.x * blockDim.x + threadIdx.x; i < EE;
         i += gridDim.x * blockDim.x)
        atomicAdd(&g_deg[dst[i]], 1);
}

__global__ void scan_pass1() {  // grid 98, block 1024
    __shared__ int wsum[32];
    int tid = threadIdx.x, lane = tid & 31, wid = tid >> 5;
    int idx = blockIdx.x * 1024 + tid;
    int v = (idx < NN) ? g_deg[idx] : 0;
    int x = v;
#pragma unroll
    for (int o = 1; o < 32; o <<= 1) {
        int t = __shfl_up_sync(0xffffffffu, x, o);
        if (lane >= o) x += t;
    }
    if (lane == 31) wsum[wid] = x;
    __syncthreads();
    if (wid == 0) {
        int y = wsum[lane];
#pragma unroll
        for (int o = 1; o < 32; o <<= 1) {
            int t = __shfl_up_sync(0xffffffffu, y, o);
            if (lane >= o) y += t;
        }
        wsum[lane] = y;
    }
    __syncthreads();
    int pre = (wid > 0) ? wsum[wid - 1] : 0;
    int incl = pre + x;
    if (idx < NN) g_off[idx] = incl - v;
    if (tid == 1023) g_bsum[blockIdx.x] = incl;
}

__global__ void scan_pass2() {  // 1 block, 128 threads
    __shared__ int wsum[4];
    int tid = threadIdx.x, lane = tid & 31, wid = tid >> 5;
    int v = (tid < 98) ? g_bsum[tid] : 0;
    int x = v;
#pragma unroll
    for (int o = 1; o < 32; o <<= 1) {
        int t = __shfl_up_sync(0xffffffffu, x, o);
        if (lane >= o) x += t;
    }
    if (lane == 31) wsum[wid] = x;
    __syncthreads();
    if (tid == 0) {
        int a = 0;
#pragma unroll
        for (int i = 0; i < 4; ++i) { int t = wsum[i]; wsum[i] = a; a += t; }
    }
    __syncthreads();
    int incl = wsum[wid] + x;
    if (tid < 98) g_boff[tid] = incl - v;
    if (tid == 127) g_off[NN] = incl;
}

__global__ void scan_pass3() {  // grid 98, block 1024
    int idx = blockIdx.x * 1024 + threadIdx.x;
    if (idx < NN) {
        int o = g_off[idx] + g_boff[blockIdx.x];
        g_off[idx] = o;
        g_cur[idx] = o;
    }
}

__global__ void scatter_kernel(const int* __restrict__ src,
                               const int* __restrict__ dst) {
    for (int i = blockIdx.x * blockDim.x + threadIdx.x; i < EE;
         i += gridDim.x * blockDim.x) {
        int d = dst[i];
        int p = atomicAdd(&g_cur[d], 1);
        g_csr[p] = src[i];
    }
}

// ---------------- fused aggregate + residual + LayerNorm --------------------
__global__ void __launch_bounds__(256)
aggregate_kernel(const float* __restrict__ gbias, const float* __restrict__ lng,
                 const float* __restrict__ lnb, float* __restrict__ hout,
                 __half* __restrict__ hh) {
    int lane = threadIdx.x & 31;
    int n = blockIdx.x * 8 + (threadIdx.x >> 5);
    int head = lane >> 2;

    float edn = g_ed[n * 8 + head];
    float e0 = g_es[n * 8 + head] + edn;
    e0 = (e0 > 0.f) ? e0 : 0.2f * e0;
    float w0 = __expf(e0);

    float d = w0;
    uint2 hv0 = *(const uint2*)&g_xhh[(long)n * 128 + lane * 4];
    __half2 q0, q1;
    memcpy(&q0, &hv0.x, 4);
    memcpy(&q1, &hv0.y, 4);
    float2 f0 = __half22float2(q0);
    float2 f1 = __half22float2(q1);
    float4 acc;
    acc.x = w0 * f0.x; acc.y = w0 * f0.y; acc.z = w0 * f1.x; acc.w = w0 * f1.y;

    int beg = g_off[n], end = g_off[n + 1];
#pragma unroll 4
    for (int j = beg; j < end; ++j) {
        int s = g_csr[j];
        float e = __ldg(&g_es[s * 8 + head]) + edn;
        e = (e > 0.f) ? e : 0.2f * e;
        float w = __expf(e);
        uint2 hv = *(const uint2*)&g_xhh[(long)s * 128 + lane * 4];
        __half2 a0, a1;
        memcpy(&a0, &hv.x, 4);
        memcpy(&a1, &hv.y, 4);
        float2 v0 = __half22float2(a0);
        float2 v1 = __half22float2(a1);
        acc.x = fmaf(w, v0.x, acc.x);
        acc.y = fmaf(w, v0.y, acc.y);
        acc.z = fmaf(w, v1.x, acc.z);
        acc.w = fmaf(w, v1.y, acc.w);
        d += w;
    }
    float invd = 1.f / (d + 1e-16f);

    const float4* hin4 = (const float4*)g_h;
    float4 h0 = hin4[n * 32 + lane];
    float4 b4 = ((const float4*)gbias)[lane];
    float4 v;
    v.x = h0.x + acc.x * invd + b4.x;
    v.y = h0.y + acc.y * invd + b4.y;
    v.z = h0.z + acc.z * invd + b4.z;
    v.w = h0.w + acc.w * invd + b4.w;

    float s1 = v.x + v.y + v.z + v.w;
#pragma unroll
    for (int o = 16; o; o >>= 1) s1 += __shfl_xor_sync(0xffffffffu, s1, o);
    float mean = s1 * (1.f / 128.f);
    float cx = v.x - mean, cy = v.y - mean, cz = v.z - mean, cw = v.w - mean;
    float s2 = cx * cx + cy * cy + cz * cz + cw * cw;
#pragma unroll
    for (int o = 16; o; o >>= 1) s2 += __shfl_xor_sync(0xffffffffu, s2, o);
    float rs = rsqrtf(s2 * (1.f / 128.f) + 1e-5f);

    float4 g4 = ((const float4*)lng)[lane];
    float4 lb4 = ((const float4*)lnb)[lane];
    float4 o;
    o.x = fmaf(cx * rs, g4.x, lb4.x);
    o.y = fmaf(cy * rs, g4.y, lb4.y);
    o.z = fmaf(cz * rs, g4.z, lb4.z);
    o.w = fmaf(cw * rs, g4.w, lb4.w);
    ((float4*)hout)[n * 32 + lane] = o;
    if (hh) {
        __half2 ph0 = __floats2half2_rn(o.x, o.y);
        __half2 ph1 = __floats2half2_rn(o.z, o.w);
        uint2 u;
        memcpy(&u.x, &ph0, 4);
        memcpy(&u.y, &ph1, 4);
        *(uint2*)&hh[(long)n * 128 + lane * 4] = u;
    }
}

// ---------------- pooling + heads --------------------------------------------
__global__ void pool_partial(const float* __restrict__ hf) {
    int col = threadIdx.x;
    int b = blockIdx.x;
    int r0 = b * 98;
    int r1 = min(NN, r0 + 98);
    double a = 0.0;
    for (int r = r0; r < r1; ++r) a += (double)hf[(long)r * 128 + col];
    g_part[b * 128 + col] = a;
}

__global__ void head_kernel(const float* __restrict__ Wmu,
                            const float* __restrict__ bmu,
                            const float* __restrict__ Wlv,
                            const float* __restrict__ blv,
                            float* __restrict__ out) {
    __shared__ float p[128];
    int t = threadIdx.x;
    double s = 0.0;
    for (int b = 0; b < 1024; ++b) s += g_part[b * 128 + t];
    float pf = (float)(s / (double)NN);
    p[t] = pf;
    __syncthreads();
    float mu = bmu[t], lv = blv[t];
#pragma unroll 8
    for (int k = 0; k < 128; ++k) {
        float pk = p[k];
        mu = fmaf(pk, Wmu[t * 128 + k], mu);
        lv = fmaf(pk, Wlv[t * 128 + k], lv);
    }
    out[t] = mu;
    out[128 + t] = lv;
    out[256 + (long)NN * 128 + t] = pf;
}

// ---------------- launch -----------------------------------------------------
extern "C" void kernel_launch(void* const* d_in, const int* in_sizes, int n_in,
                              void* d_out, int out_size) {
    const float* x      = (const float*)d_in[0];
    const int*   ei     = (const int*)d_in[1];
    const float* W_in   = (const float*)d_in[2];
    const float* b_in   = (const float*)d_in[3];
    const float* gat_W  = (const float*)d_in[4];
    const float* attsrc = (const float*)d_in[5];
    const float* attdst = (const float*)d_in[6];
    const float* gat_b  = (const float*)d_in[7];
    const float* ln_g   = (const float*)d_in[8];
    const float* ln_b   = (const float*)d_in[9];
    const float* W_mu   = (const float*)d_in[10];
    const float* b_mu   = (const float*)d_in[11];
    const float* W_lv   = (const float*)d_in[12];
    const float* b_lv   = (const float*)d_in[13];
    float* out = (float*)d_out;

    void *p_h, *p_hh, *p_whin, *p_wh;
    cudaGetSymbolAddress(&p_h, g_h);
    cudaGetSymbolAddress(&p_hh, g_hh);
    cudaGetSymbolAddress(&p_whin, g_Whin);
    cudaGetSymbolAddress(&p_wh, g_Wh);
    float* hbuf = (float*)p_h;
    __half* hhbuf = (__half*)p_hh;
    const __half* whinbuf = (const __half*)p_whin;
    const __half* whbuf = (const __half*)p_wh;

    cudaFuncSetAttribute((const void*)gemm_hmma_kernel<256, true, false>,
                         cudaFuncAttributeMaxDynamicSharedMemorySize, HS_TOT);
    cudaFuncSetAttribute((const void*)gemm_hmma_kernel<128, false, true>,
                         cudaFuncAttributeMaxDynamicSharedMemorySize, HS_TOT);

    const int gridtc = (NN + 127) / 128;   // 782

    // profiler captures launch #4 -> layer-0 HMMA GEMM.
    transpose_weights<<<775, 256>>>(W_in, gat_W);                       // 1
    gemm_hmma_kernel<256, true, false><<<gridtc, 256, HS_TOT>>>(        // 2
        x, whinbuf, b_in, hbuf, nullptr, nullptr);
    hist_kernel<<<1024, 256>>>(ei + EE);                                // 3
    gemm_hmma_kernel<128, false, true><<<gridtc, 256, HS_TOT>>>(        // 4 (profiled)
        hhbuf, whbuf, nullptr, nullptr, attsrc, attdst);
    scan_pass1<<<98, 1024>>>();                                         // 5
    scan_pass2<<<1, 128>>>();                                           // 6
    scan_pass3<<<98, 1024>>>();                                         // 7
    scatter_kernel<<<1024, 256>>>(ei, ei + EE);                         // 8

    for (int l = 0; l < 4; ++l) {
        if (l > 0) {
            gemm_hmma_kernel<128, false, true><<<gridtc, 256, HS_TOT>>>(
                hhbuf, whbuf + l * 16384, nullptr, nullptr,
                attsrc + l * 128, attdst + l * 128);
        }
        aggregate_kernel<<<NN / 8, 256>>>(gat_b + l * 128, ln_g + l * 128,
                                          ln_b + l * 128,
                                          (l == 3) ? (out + 256) : hbuf,
                                          (l == 3) ? nullptr : hhbuf);
    }

    pool_partial<<<1024, 128>>>(out + 256);
    head_kernel<<<1, 128>>>(W_mu, b_mu, W_lv, b_lv, out);
}

// round 13
// speedup vs baseline: 1.7363x; 1.0234x over previous
#include <cuda_runtime.h>
#include <cuda_fp16.h>
#include <string.h>
#include <stdint.h>

#define NN 100000
#define EE 1600000
#define DD 128
#define HH 8

typedef unsigned long long ull;

// ---------------- scratch (device globals; no allocations allowed) ----------
__device__ __align__(16) float  g_h[NN * DD];    // hidden state fp32 (residual)
__device__ __align__(16) __half g_hh[NN * DD];   // hidden state fp16 (MMA input)
__device__ __align__(16) __half g_xhh[NN * DD];  // transformed feats fp16
__device__ __align__(16) __half g_es[NN * HH];   // src attn logits (fp16)
__device__ __align__(16) __half g_ed[NN * HH];   // dst attn logits (fp16)
__device__ int   g_deg[NN];
__device__ int   g_off[NN + 1];
__device__ int   g_cur[NN];
__device__ int   g_csr[EE];
__device__ int   g_bsum[128];
__device__ int   g_boff[128];
__device__ double g_part[1024 * DD];
__device__ __align__(16) __half g_Whin[DD * 256];    // W_in fp16 [n][k]
__device__ __align__(16) __half g_Wh[4 * DD * DD];   // gat_W fp16 [l][n][k]

// single dynamic-smem symbol shared by all kernels
extern __shared__ char dynsmem[];

__device__ __forceinline__ uint32_t smem_u32(const void* p) {
    uint32_t a;
    asm("{ .reg .u64 t; cvta.to.shared.u64 t, %1; cvt.u32.u64 %0, t; }"
        : "=r"(a) : "l"(p));
    return a;
}

// ---------------- weight fp16 convert ----------------------------------------
__global__ void transpose_weights(const float* __restrict__ Win,
                                  const float* __restrict__ gw) {
    int idx = blockIdx.x * blockDim.x + threadIdx.x;
    if (idx < 32768) {
        g_Whin[idx] = __float2half(Win[idx]);       // [n][k] as-is
    } else if (idx < 98304) {
        int r = idx - 32768;
        g_Wh[r] = __float2half(gw[r]);              // [l][n][k] as-is
    }
}

__global__ void zero_deg_kernel() {
    int idx = blockIdx.x * blockDim.x + threadIdx.x;
    if (idx < NN) g_deg[idx] = 0;
}

// ---------------- unified HMMA GEMM ------------------------------------------
// C[M,128] = A[M,K] @ B^T (B = [128 n][K k] fp16). 128x128 tile per CTA,
// 8 warps x (16 rows x 128 cols), mma.m16n8k16 f16->f32, K chunked by 128.
#define HS_A 0
#define HS_B 32768
#define HS_AS 65536
#define HS_AD 66048
#define HS_TOT 66560

__device__ __forceinline__ void ldsm_x4(uint32_t& r0, uint32_t& r1,
                                        uint32_t& r2, uint32_t& r3,
                                        uint32_t addr) {
    asm volatile(
        "ldmatrix.sync.aligned.m8n8.x4.shared.b16 {%0,%1,%2,%3}, [%4];"
        : "=r"(r0), "=r"(r1), "=r"(r2), "=r"(r3) : "r"(addr));
}

__device__ __forceinline__ void mma16816(float* c, uint32_t a0, uint32_t a1,
                                         uint32_t a2, uint32_t a3,
                                         uint32_t b0, uint32_t b1) {
    asm volatile(
        "mma.sync.aligned.m16n8k16.row.col.f32.f16.f16.f32 "
        "{%0,%1,%2,%3}, {%4,%5,%6,%7}, {%8,%9}, {%0,%1,%2,%3};"
        : "+f"(c[0]), "+f"(c[1]), "+f"(c[2]), "+f"(c[3])
        : "r"(a0), "r"(a1), "r"(a2), "r"(a3), "r"(b0), "r"(b1));
}

__device__ __forceinline__ uint32_t pack_h2(float a, float b) {
    __half2 h = __floats2half2_rn(a, b);
    uint32_t u;
    memcpy(&u, &h, 4);
    return u;
}

template <int K, bool AFP32, bool ATTN>
__global__ void __launch_bounds__(256, 2)
gemm_hmma_kernel(const void* __restrict__ Asrc, const __half* __restrict__ Bh,
                 const float* __restrict__ bias, float* __restrict__ Cout,
                 const float* __restrict__ asrc, const float* __restrict__ adst) {
    char* smem = dynsmem;
    uint32_t sb = smem_u32(smem);
    int tid = threadIdx.x;
    int lane = tid & 31;
    int wid = tid >> 5;
    long row0 = (long)blockIdx.x * 128;

    int m0 = wid * 16;
    float acc[16][4];
#pragma unroll
    for (int t = 0; t < 16; ++t)
#pragma unroll
        for (int i = 0; i < 4; ++i) acc[t][i] = 0.f;

    int l15 = lane & 15;
    int khalf = lane >> 4;
    int ar = m0 + l15;

    for (int kk = 0; kk < K; kk += 128) {
        if (kk) __syncthreads();
#pragma unroll
        for (int p = 0; p < 8; ++p) {
            int lin = p * 256 + tid;       // 0..2047 chunks
            int r = lin >> 4;              // row 0..127
            int c = lin & 15;              // 16B chunk 0..15
            int swc = c ^ (r & 7);
            long grow = row0 + r;
            uint4 va = make_uint4(0, 0, 0, 0);
            if (grow < NN) {
                if (AFP32) {
                    const float* ax = (const float*)Asrc + grow * K + kk + c * 8;
                    float4 f0 = *(const float4*)ax;
                    float4 f1 = *(const float4*)(ax + 4);
                    va.x = pack_h2(f0.x, f0.y);
                    va.y = pack_h2(f0.z, f0.w);
                    va.z = pack_h2(f1.x, f1.y);
                    va.w = pack_h2(f1.z, f1.w);
                } else {
                    va = *(const uint4*)((const __half*)Asrc + grow * 128 + c * 8);
                }
            }
            *(uint4*)(smem + HS_A + r * 256 + swc * 16) = va;
            uint4 vb = *(const uint4*)&Bh[(long)r * K + kk + c * 8];
            *(uint4*)(smem + HS_B + r * 256 + swc * 16) = vb;
        }
        if (kk == 0 && tid < 128) {
            if (ATTN) {
                ((float*)(smem + HS_AS))[tid] = asrc[tid];
                ((float*)(smem + HS_AD))[tid] = adst[tid];
            }
            if (AFP32) ((float*)(smem + HS_AS))[tid] = bias[tid];
        }
        __syncthreads();

#pragma unroll
        for (int ks = 0; ks < 8; ++ks) {
            int kc = ks * 2 + khalf;
            uint32_t a0, a1, a2, a3;
            ldsm_x4(a0, a1, a2, a3,
                    sb + HS_A + ar * 256 + (kc ^ (ar & 7)) * 16);
#pragma unroll
            for (int j = 0; j < 8; ++j) {
                int br = j * 16 + l15;
                uint32_t b0, b1, b2, b3;
                ldsm_x4(b0, b1, b2, b3,
                        sb + HS_B + br * 256 + (kc ^ (br & 7)) * 16);
                mma16816(acc[2 * j], a0, a1, a2, a3, b0, b2);
                mma16816(acc[2 * j + 1], a0, a1, a2, a3, b1, b3);
            }
        }
    }

    // epilogue
    int rlo = m0 + (lane >> 2);
    long glo = row0 + rlo;
    long ghi = glo + 8;
    bool vlo = (glo < NN), vhi = (ghi < NN);

    if (AFP32) {
        const float* sbias = (const float*)(smem + HS_AS);
#pragma unroll
        for (int t = 0; t < 16; ++t) {
            int col = t * 8 + (lane & 3) * 2;
            float b0 = sbias[col], b1 = sbias[col + 1];
            float c0 = acc[t][0] + b0, c1 = acc[t][1] + b1;
            float c2 = acc[t][2] + b0, c3 = acc[t][3] + b1;
            if (vlo) {
                *(float2*)&Cout[glo * 128 + col] = make_float2(c0, c1);
                *(__half2*)&g_hh[glo * 128 + col] = __floats2half2_rn(c0, c1);
            }
            if (vhi) {
                *(float2*)&Cout[ghi * 128 + col] = make_float2(c2, c3);
                *(__half2*)&g_hh[ghi * 128 + col] = __floats2half2_rn(c2, c3);
            }
        }
    }
    if (ATTN) {
        const float* s_as = (const float*)(smem + HS_AS);
        const float* s_ad = (const float*)(smem + HS_AD);
        float eslo[8], edlo[8], eshi[8], edhi[8];
#pragma unroll
        for (int h = 0; h < 8; ++h) { eslo[h] = edlo[h] = eshi[h] = edhi[h] = 0.f; }
#pragma unroll
        for (int t = 0; t < 16; ++t) {
            int col = t * 8 + (lane & 3) * 2;
            int h = t >> 1;
            float c0 = acc[t][0], c1 = acc[t][1];
            float c2 = acc[t][2], c3 = acc[t][3];
            if (vlo) *(__half2*)&g_xhh[glo * 128 + col] = __floats2half2_rn(c0, c1);
            if (vhi) *(__half2*)&g_xhh[ghi * 128 + col] = __floats2half2_rn(c2, c3);
            float as0 = s_as[col], as1 = s_as[col + 1];
            float ad0 = s_ad[col], ad1 = s_ad[col + 1];
            eslo[h] += c0 * as0 + c1 * as1;
            edlo[h] += c0 * ad0 + c1 * ad1;
            eshi[h] += c2 * as0 + c3 * as1;
            edhi[h] += c2 * ad0 + c3 * ad1;
        }
#pragma unroll
        for (int h = 0; h < 8; ++h) {
            eslo[h] += __shfl_xor_sync(0xffffffffu, eslo[h], 1);
            eslo[h] += __shfl_xor_sync(0xffffffffu, eslo[h], 2);
            edlo[h] += __shfl_xor_sync(0xffffffffu, edlo[h], 1);
            edlo[h] += __shfl_xor_sync(0xffffffffu, edlo[h], 2);
            eshi[h] += __shfl_xor_sync(0xffffffffu, eshi[h], 1);
            eshi[h] += __shfl_xor_sync(0xffffffffu, eshi[h], 2);
            edhi[h] += __shfl_xor_sync(0xffffffffu, edhi[h], 1);
            edhi[h] += __shfl_xor_sync(0xffffffffu, edhi[h], 2);
        }
        if ((lane & 3) == 0) {
            if (vlo) {
                uint4 ue = make_uint4(pack_h2(eslo[0], eslo[1]), pack_h2(eslo[2], eslo[3]),
                                      pack_h2(eslo[4], eslo[5]), pack_h2(eslo[6], eslo[7]));
                *(uint4*)&g_es[glo * 8] = ue;
                uint4 ud = make_uint4(pack_h2(edlo[0], edlo[1]), pack_h2(edlo[2], edlo[3]),
                                      pack_h2(edlo[4], edlo[5]), pack_h2(edlo[6], edlo[7]));
                *(uint4*)&g_ed[glo * 8] = ud;
            }
            if (vhi) {
                uint4 ue = make_uint4(pack_h2(eshi[0], eshi[1]), pack_h2(eshi[2], eshi[3]),
                                      pack_h2(eshi[4], eshi[5]), pack_h2(eshi[6], eshi[7]));
                *(uint4*)&g_es[ghi * 8] = ue;
                uint4 ud = make_uint4(pack_h2(edhi[0], edhi[1]), pack_h2(edhi[2], edhi[3]),
                                      pack_h2(edhi[4], edhi[5]), pack_h2(edhi[6], edhi[7]));
                *(uint4*)&g_ed[ghi * 8] = ud;
            }
        }
    }
}

// ---------------- CSR build --------------------------------------------------
__global__ void hist_kernel(const int* __restrict__ dst) {
    for (int i = blockIdx.x * blockDim.x + threadIdx.x; i < EE;
         i += gridDim.x * blockDim.x)
        atomicAdd(&g_deg[dst[i]], 1);
}

__global__ void scan_pass1() {  // grid 98, block 1024
    __shared__ int wsum[32];
    int tid = threadIdx.x, lane = tid & 31, wid = tid >> 5;
    int idx = blockIdx.x * 1024 + tid;
    int v = (idx < NN) ? g_deg[idx] : 0;
    int x = v;
#pragma unroll
    for (int o = 1; o < 32; o <<= 1) {
        int t = __shfl_up_sync(0xffffffffu, x, o);
        if (lane >= o) x += t;
    }
    if (lane == 31) wsum[wid] = x;
    __syncthreads();
    if (wid == 0) {
        int y = wsum[lane];
#pragma unroll
        for (int o = 1; o < 32; o <<= 1) {
            int t = __shfl_up_sync(0xffffffffu, y, o);
            if (lane >= o) y += t;
        }
        wsum[lane] = y;
    }
    __syncthreads();
    int pre = (wid > 0) ? wsum[wid - 1] : 0;
    int incl = pre + x;
    if (idx < NN) g_off[idx] = incl - v;
    if (tid == 1023) g_bsum[blockIdx.x] = incl;
}

__global__ void scan_pass2() {  // 1 block, 128 threads
    __shared__ int wsum[4];
    int tid = threadIdx.x, lane = tid & 31, wid = tid >> 5;
    int v = (tid < 98) ? g_bsum[tid] : 0;
    int x = v;
#pragma unroll
    for (int o = 1; o < 32; o <<= 1) {
        int t = __shfl_up_sync(0xffffffffu, x, o);
        if (lane >= o) x += t;
    }
    if (lane == 31) wsum[wid] = x;
    __syncthreads();
    if (tid == 0) {
        int a = 0;
#pragma unroll
        for (int i = 0; i < 4; ++i) { int t = wsum[i]; wsum[i] = a; a += t; }
    }
    __syncthreads();
    int incl = wsum[wid] + x;
    if (tid < 98) g_boff[tid] = incl - v;
    if (tid == 127) g_off[NN] = incl;
}

__global__ void scan_pass3() {  // grid 98, block 1024
    int idx = blockIdx.x * 1024 + threadIdx.x;
    if (idx < NN) {
        int o = g_off[idx] + g_boff[blockIdx.x];
        g_off[idx] = o;
        g_cur[idx] = o;
    }
}

__global__ void scatter_kernel(const int* __restrict__ src,
                               const int* __restrict__ dst) {
    for (int i = blockIdx.x * blockDim.x + threadIdx.x; i < EE;
         i += gridDim.x * blockDim.x) {
        int d = dst[i];
        int p = atomicAdd(&g_cur[d], 1);
        g_csr[p] = src[i];
    }
}

// ---------------- fused aggregate + residual + LayerNorm --------------------
__global__ void __launch_bounds__(256)
aggregate_kernel(const float* __restrict__ gbias, const float* __restrict__ lng,
                 const float* __restrict__ lnb, float* __restrict__ hout,
                 __half* __restrict__ hh) {
    int lane = threadIdx.x & 31;
    int n = blockIdx.x * 8 + (threadIdx.x >> 5);
    int head = lane >> 2;

    float edn = __half2float(g_ed[n * 8 + head]);
    float e0 = __half2float(g_es[n * 8 + head]) + edn;
    e0 = (e0 > 0.f) ? e0 : 0.2f * e0;
    float w0 = __expf(e0);

    float d = w0;
    uint2 hv0 = *(const uint2*)&g_xhh[(long)n * 128 + lane * 4];
    __half2 q0, q1;
    memcpy(&q0, &hv0.x, 4);
    memcpy(&q1, &hv0.y, 4);
    float2 f0 = __half22float2(q0);
    float2 f1 = __half22float2(q1);
    float4 acc;
    acc.x = w0 * f0.x; acc.y = w0 * f0.y; acc.z = w0 * f1.x; acc.w = w0 * f1.y;

    int beg = g_off[n], end = g_off[n + 1];
#pragma unroll 4
    for (int j = beg; j < end; ++j) {
        int s = g_csr[j];
        float e = __half2float(__ldg(&g_es[s * 8 + head])) + edn;
        e = (e > 0.f) ? e : 0.2f * e;
        float w = __expf(e);
        uint2 hv = *(const uint2*)&g_xhh[(long)s * 128 + lane * 4];
        __half2 a0, a1;
        memcpy(&a0, &hv.x, 4);
        memcpy(&a1, &hv.y, 4);
        float2 v0 = __half22float2(a0);
        float2 v1 = __half22float2(a1);
        acc.x = fmaf(w, v0.x, acc.x);
        acc.y = fmaf(w, v0.y, acc.y);
        acc.z = fmaf(w, v1.x, acc.z);
        acc.w = fmaf(w, v1.y, acc.w);
        d += w;
    }
    float invd = 1.f / (d + 1e-16f);

    const float4* hin4 = (const float4*)g_h;
    float4 h0 = hin4[n * 32 + lane];
    float4 b4 = ((const float4*)gbias)[lane];
    float4 v;
    v.x = h0.x + acc.x * invd + b4.x;
    v.y = h0.y + acc.y * invd + b4.y;
    v.z = h0.z + acc.z * invd + b4.z;
    v.w = h0.w + acc.w * invd + b4.w;

    float s1 = v.x + v.y + v.z + v.w;
#pragma unroll
    for (int o = 16; o; o >>= 1) s1 += __shfl_xor_sync(0xffffffffu, s1, o);
    float mean = s1 * (1.f / 128.f);
    float cx = v.x - mean, cy = v.y - mean, cz = v.z - mean, cw = v.w - mean;
    float s2 = cx * cx + cy * cy + cz * cz + cw * cw;
#pragma unroll
    for (int o = 16; o; o >>= 1) s2 += __shfl_xor_sync(0xffffffffu, s2, o);
    float rs = rsqrtf(s2 * (1.f / 128.f) + 1e-5f);

    float4 g4 = ((const float4*)lng)[lane];
    float4 lb4 = ((const float4*)lnb)[lane];
    float4 o;
    o.x = fmaf(cx * rs, g4.x, lb4.x);
    o.y = fmaf(cy * rs, g4.y, lb4.y);
    o.z = fmaf(cz * rs, g4.z, lb4.z);
    o.w = fmaf(cw * rs, g4.w, lb4.w);
    ((float4*)hout)[n * 32 + lane] = o;
    if (hh) {
        __half2 ph0 = __floats2half2_rn(o.x, o.y);
        __half2 ph1 = __floats2half2_rn(o.z, o.w);
        uint2 u;
        memcpy(&u.x, &ph0, 4);
        memcpy(&u.y, &ph1, 4);
        *(uint2*)&hh[(long)n * 128 + lane * 4] = u;
    }
}

// ---------------- pooling + heads --------------------------------------------
__global__ void pool_partial(const float* __restrict__ hf) {
    int col = threadIdx.x;
    int b = blockIdx.x;
    int r0 = b * 98;
    int r1 = min(NN, r0 + 98);
    double a = 0.0;
    for (int r = r0; r < r1; ++r) a += (double)hf[(long)r * 128 + col];
    g_part[b * 128 + col] = a;
}

__global__ void head_kernel(const float* __restrict__ Wmu,
                            const float* __restrict__ bmu,
                            const float* __restrict__ Wlv,
                            const float* __restrict__ blv,
                            float* __restrict__ out) {
    __shared__ float p[128];
    int t = threadIdx.x;
    double s = 0.0;
    for (int b = 0; b < 1024; ++b) s += g_part[b * 128 + t];
    float pf = (float)(s / (double)NN);
    p[t] = pf;
    __syncthreads();
    float mu = bmu[t], lv = blv[t];
#pragma unroll 8
    for (int k = 0; k < 128; ++k) {
        float pk = p[k];
        mu = fmaf(pk, Wmu[t * 128 + k], mu);
        lv = fmaf(pk, Wlv[t * 128 + k], lv);
    }
    out[t] = mu;
    out[128 + t] = lv;
    out[256 + (long)NN * 128 + t] = pf;
}

// ---------------- launch -----------------------------------------------------
extern "C" void kernel_launch(void* const* d_in, const int* in_sizes, int n_in,
                              void* d_out, int out_size) {
    const float* x      = (const float*)d_in[0];
    const int*   ei     = (const int*)d_in[1];
    const float* W_in   = (const float*)d_in[2];
    const float* b_in   = (const float*)d_in[3];
    const float* gat_W  = (const float*)d_in[4];
    const float* attsrc = (const float*)d_in[5];
    const float* attdst = (const float*)d_in[6];
    const float* gat_b  = (const float*)d_in[7];
    const float* ln_g   = (const float*)d_in[8];
    const float* ln_b   = (const float*)d_in[9];
    const float* W_mu   = (const float*)d_in[10];
    const float* b_mu   = (const float*)d_in[11];
    const float* W_lv   = (const float*)d_in[12];
    const float* b_lv   = (const float*)d_in[13];
    float* out = (float*)d_out;

    void *p_h, *p_hh, *p_whin, *p_wh;
    cudaGetSymbolAddress(&p_h, g_h);
    cudaGetSymbolAddress(&p_hh, g_hh);
    cudaGetSymbolAddress(&p_whin, g_Whin);
    cudaGetSymbolAddress(&p_wh, g_Wh);
    float* hbuf = (float*)p_h;
    __half* hhbuf = (__half*)p_hh;
    const __half* whinbuf = (const __half*)p_whin;
    const __half* whbuf = (const __half*)p_wh;

    cudaFuncSetAttribute((const void*)gemm_hmma_kernel<256, true, false>,
                         cudaFuncAttributeMaxDynamicSharedMemorySize, HS_TOT);
    cudaFuncSetAttribute((const void*)gemm_hmma_kernel<128, false, true>,
                         cudaFuncAttributeMaxDynamicSharedMemorySize, HS_TOT);

    const int gridtc = (NN + 127) / 128;   // 782

    // fork a non-blocking side stream: CSR build runs concurrently with the
    // front GEMMs (no data dependence until the first aggregate).
    cudaStream_t s2;
    cudaStreamCreateWithFlags(&s2, cudaStreamNonBlocking);
    cudaEvent_t ev0, ev1;
    cudaEventCreateWithFlags(&ev0, cudaEventDisableTiming);
    cudaEventCreateWithFlags(&ev1, cudaEventDisableTiming);

    cudaEventRecord(ev0, 0);
    cudaStreamWaitEvent(s2, ev0, 0);
    zero_deg_kernel<<<98, 1024, 0, s2>>>();
    hist_kernel<<<1024, 256, 0, s2>>>(ei + EE);
    scan_pass1<<<98, 1024, 0, s2>>>();
    scan_pass2<<<1, 128, 0, s2>>>();
    scan_pass3<<<98, 1024, 0, s2>>>();
    scatter_kernel<<<1024, 256, 0, s2>>>(ei, ei + EE);
    cudaEventRecord(ev1, s2);

    // main stream: weights -> input GEMM -> layer-0 GEMM
    transpose_weights<<<384, 256>>>(W_in, gat_W);
    gemm_hmma_kernel<256, true, false><<<gridtc, 256, HS_TOT>>>(
        x, whinbuf, b_in, hbuf, nullptr, nullptr);
    gemm_hmma_kernel<128, false, true><<<gridtc, 256, HS_TOT>>>(
        hhbuf, whbuf, nullptr, nullptr, attsrc, attdst);

    cudaStreamWaitEvent(0, ev1, 0);   // join: aggregates need the CSR

    for (int l = 0; l < 4; ++l) {
        if (l > 0) {
            gemm_hmma_kernel<128, false, true><<<gridtc, 256, HS_TOT>>>(
                hhbuf, whbuf + l * 16384, nullptr, nullptr,
                attsrc + l * 128, attdst + l * 128);
        }
        aggregate_kernel<<<NN / 8, 256>>>(gat_b + l * 128, ln_g + l * 128,
                                          ln_b + l * 128,
                                          (l == 3) ? (out + 256) : hbuf,
                                          (l == 3) ? nullptr : hhbuf);
    }

    pool_partial<<<1024, 128>>>(out + 256);
    head_kernel<<<1, 128>>>(W_mu, b_mu, W_lv, b_lv, out);
}